// round 15
// baseline (speedup 1.0000x reference)
#include <cuda_runtime.h>
#include <math.h>
#include <stdint.h>

#define BB  64
#define WW  128
#define KK  64
#define KSZ 7
#define EFD 128
#define ETD 128
#define HH  256
#define FHD 256
#define G3  768   // 3*H
#define ZC  192   // 3*K

// ---------------- scratch (static device globals; no runtime alloc) ----------------
__device__ __align__(16) float g_y[BB*WW*KK];
__device__ __align__(16) float g_hfeat[BB*WW*KK];
__device__ __align__(16) float g_htemp[BB*WW*KK];
__device__ __align__(16) float g_p[BB*WW*ETD];
__device__ __align__(16) float g_q[BB*WW*ETD];
__device__ __align__(16) float g_gi[BB*WW*G3];
__device__ float g_h[BB*HH];
__device__ __align__(16) float g_cwT[KSZ*KK*KK];   // [s][i][k]
__device__ __align__(16) float g_tlwT[ETD*ETD];    // [c][e] (legacy)
__device__ __align__(16) float g_whhR[4*96*256*2]; // [slice][i=g*32+jl][col=hq*64+u][par]
__device__ __align__(16) float g_fc0T[FHD*FHD];
__device__ __align__(16) float g_fc1T[FHD*FHD];
__device__ __align__(16) float g_fc2T[FHD*FHD];
__device__ __align__(16) float g_fc3T[FHD*KK];
__device__ float g_u1[WW];
__device__ float g_u2[WW];
__device__ float g_c12[2];

__device__ __forceinline__ float sigm(float x){ return 1.f/(1.f+__expf(-x)); }
__device__ __forceinline__ float tanh_fast(float x){
    float e2 = __expf(2.f*x);
    return 1.f - 2.f/(e2+1.f);
}
__device__ __forceinline__ float lrelu(float v){ return fmaxf(v, 0.2f*v); } // ALPHA=0.2<1

__device__ __forceinline__ uint32_t smem_u32(const void* p){
    uint32_t a;
    asm("{ .reg .u64 t0; cvta.to.shared.u64 t0, %1; cvt.u32.u64 %0, t0; }" : "=r"(a) : "l"(p));
    return a;
}
__device__ __forceinline__ void fma2(unsigned long long& a, unsigned long long w, unsigned long long h){
    asm("fma.rn.f32x2 %0, %1, %2, %0;" : "+l"(a) : "l"(w), "l"(h));
}
__device__ __forceinline__ float ull_sum(unsigned long long v){
    unsigned lo, hi;
    asm("mov.b64 {%0,%1}, %2;" : "=r"(lo), "=r"(hi) : "l"(v));
    return __uint_as_float(lo) + __uint_as_float(hi);
}
__device__ __forceinline__ unsigned long long bcast2(float v){
    unsigned long long r;
    asm("mov.b64 %0, {%1, %1};" : "=l"(r) : "r"(__float_as_uint(v)));
    return r;
}
__device__ __forceinline__ void mbar_init(uint32_t mb, uint32_t cnt){
    asm volatile("mbarrier.init.shared.b64 [%0], %1;" :: "r"(mb), "r"(cnt) : "memory");
}
__device__ __forceinline__ void mbar_expect(uint32_t mb, uint32_t tx){
    asm volatile("mbarrier.arrive.expect_tx.shared.b64 _, [%0], %1;" :: "r"(mb), "r"(tx) : "memory");
}
__device__ __forceinline__ void mbar_wait(uint32_t mb, int parity){
    asm volatile(
        "{\n\t.reg .pred P1;\n\t"
        "WL_%=:\n\t"
        "mbarrier.try_wait.parity.acquire.cta.shared::cta.b64 P1, [%0], %1, 0x989680;\n\t"
        "@P1 bra.uni WD_%=;\n\t"
        "bra.uni WL_%=;\n\t"
        "WD_%=:\n\t}"
        :: "r"(mb), "r"(parity) : "memory");
}
__device__ __forceinline__ uint32_t mapa_u32(uint32_t a, uint32_t rank){
    uint32_t r;
    asm("mapa.shared::cluster.u32 %0, %1, %2;" : "=r"(r) : "r"(a), "r"(rank));
    return r;
}
__device__ __forceinline__ void dsmem_bulk(uint32_t dst, uint32_t src, uint32_t bytes, uint32_t rbar){
    asm volatile("cp.async.bulk.shared::cluster.shared::cta.mbarrier::complete_tx::bytes [%0], [%1], %2, [%3];"
                 :: "r"(dst), "r"(src), "r"(bytes), "r"(rbar) : "memory");
}
__device__ __forceinline__ uint32_t to_tf32(float v){
    uint32_t r;
    asm("cvt.rna.tf32.f32 %0, %1;" : "=r"(r) : "f"(v));
    return r;
}
__device__ __forceinline__ void mma_tf32_16x8x8(float& d0, float& d1, float& d2, float& d3,
                                                uint32_t a0, uint32_t a1, uint32_t a2, uint32_t a3,
                                                uint32_t b0, uint32_t b1){
    asm volatile("mma.sync.aligned.m16n8k8.row.col.f32.tf32.tf32.f32 "
                 "{%0,%1,%2,%3}, {%4,%5,%6,%7}, {%8,%9}, {%0,%1,%2,%3};"
                 : "+f"(d0), "+f"(d1), "+f"(d2), "+f"(d3)
                 : "r"(a0), "r"(a1), "r"(a2), "r"(a3), "r"(b0), "r"(b1));
}

// ---------------- weight reshapes / transposes + u1/u2/c12 ----------------
__global__ void k_prep(const float* __restrict__ conv_w, const float* __restrict__ tlw,
                       const float* __restrict__ whh,
                       const float* __restrict__ fc0, const float* __restrict__ fc1,
                       const float* __restrict__ fc2, const float* __restrict__ fc3,
                       const float* __restrict__ flw, const float* __restrict__ flb,
                       const float* __restrict__ fa){
    int idx = blockIdx.x*blockDim.x + threadIdx.x;
    if(idx < 28672){
        int k = idx/448; int rem = idx - k*448; int i = rem/7; int s = rem - i*7;
        g_cwT[(s*64+i)*64 + k] = conv_w[idx];
        return;
    }
    idx -= 28672;
    if(idx < 16384){
        int e = idx>>7, c = idx&127;
        g_tlwT[c*128 + e] = tlw[idx];
        return;
    }
    idx -= 16384;
    if(idx < 196608){
        int o = idx>>8, j = idx&255;
        int g = o>>8;
        int ou = o&255;
        int s = ou>>6, u = ou&63;
        int hq = j>>6;
        int jl = (j&63)>>1;
        int par = j&1;
        int d = (s*96 + g*32 + jl)*256 + (hq*64 + u);
        g_whhR[d*2 + par] = whh[idx];
        return;
    }
    idx -= 196608;
    if(idx < 65536){ int o = idx>>8, j = idx&255; g_fc0T[j*256+o] = fc0[idx]; return; }
    idx -= 65536;
    if(idx < 65536){ int o = idx>>8, j = idx&255; g_fc1T[j*256+o] = fc1[idx]; return; }
    idx -= 65536;
    if(idx < 65536){ int o = idx>>8, j = idx&255; g_fc2T[j*256+o] = fc2[idx]; return; }
    idx -= 65536;
    if(idx < 16384){ int o = idx>>8, j = idx&255; g_fc3T[j*64+o] = fc3[idx]; return; }
    idx -= 16384;
    if(idx < 128){
        float a1=0.f, a2=0.f;
        for(int e=0;e<EFD;e++){ float w = flw[e*WW + idx]; a1 += w*fa[e]; a2 += w*fa[EFD+e]; }
        g_u1[idx]=a1; g_u2[idx]=a2;
        return;
    }
    if(idx==128){ float c=0.f; for(int e=0;e<EFD;e++) c += flb[e]*fa[e];     g_c12[0]=c; return; }
    if(idx==129){ float c=0.f; for(int e=0;e<EFD;e++) c += flb[e]*fa[EFD+e]; g_c12[1]=c; return; }
}

// ---------------- conv1d (pad=3) + relu -> y[b,w,k] ; f32x2 over k-pairs ----------------
__global__ void k_conv(const float* __restrict__ x, const float* __restrict__ conv_b){
    int b = blockIdx.y; int w0 = blockIdx.x*16;
    int t = threadIdx.x; // 128
    int kp = t&31, wq = t>>5;
    __shared__ float xs[22*64];
    for(int i=t; i<22*64; i+=128){
        int row = w0-3+(i>>6);
        xs[i] = (row>=0 && row<WW) ? x[(b*WW+row)*KK + (i&63)] : 0.f;
    }
    __syncthreads();
    unsigned long long acc[4];
    {
        float2 b2 = *(const float2*)(conv_b + 2*kp);
        unsigned long long bb;
        asm("mov.b64 %0, {%1, %2};" : "=l"(bb) : "r"(__float_as_uint(b2.x)), "r"(__float_as_uint(b2.y)));
        #pragma unroll
        for(int r=0;r<4;r++) acc[r]=bb;
    }
    #pragma unroll
    for(int s=0;s<KSZ;s++){
        #pragma unroll 8
        for(int i=0;i<KK;i++){
            unsigned long long cw2 = *(const unsigned long long*)(g_cwT + (s*64+i)*64 + 2*kp);
            #pragma unroll
            for(int r=0;r<4;r++){
                unsigned long long xx = bcast2(xs[(wq*4+r+s)*64 + i]);
                fma2(acc[r], cw2, xx);
            }
        }
    }
    #pragma unroll
    for(int r=0;r<4;r++){
        unsigned lo, hi;
        asm("mov.b64 {%0,%1}, %2;" : "=r"(lo), "=r"(hi) : "l"(acc[r]));
        float2 o;
        o.x = fmaxf(__uint_as_float(lo), 0.f);
        o.y = fmaxf(__uint_as_float(hi), 0.f);
        *(float2*)(g_y + (size_t)(b*WW + w0 + wq*4 + r)*KK + 2*kp) = o;
    }
}

// ---------------- feature attention + h_feat (s1/s2 fused in) ----------------
__global__ __launch_bounds__(256) void k_feat(const float* __restrict__ feat_bias){
    int b = blockIdx.x; int t = threadIdx.x; // 256
    __shared__ float ys[WW*KK];
    __shared__ float att[KK*KK];
    __shared__ float u1s[WW], u2s[WW];
    __shared__ float r1[256], r2[256];
    __shared__ float s1s[64], s2s[64];
    if(t<128){ u1s[t]=g_u1[t]; u2s[t]=g_u2[t]; }
    for(int it=0; it<32; it++){ int idx = it*256+t; ys[idx] = g_y[b*WW*KK + idx]; }
    __syncthreads();
    {
        int k = t&63, q = t>>6;
        float a1=0.f, a2=0.f;
        #pragma unroll 8
        for(int w=q*32; w<q*32+32; w++){
            float yv = ys[w*64+k];
            a1 += yv*u1s[w]; a2 += yv*u2s[w];
        }
        r1[t]=a1; r2[t]=a2;
    }
    __syncthreads();
    if(t<64){
        s1s[t] = r1[t]+r1[t+64]+r1[t+128]+r1[t+192] + g_c12[0];
        s2s[t] = r2[t]+r2[t+64]+r2[t+128]+r2[t+192] + g_c12[1];
    }
    __syncthreads();
    int lane = t&31, wd = t>>5;
    #pragma unroll
    for(int r=0;r<8;r++){
        int i = wd*8 + r;
        float s1v = s1s[i];
        int j0 = lane, j1 = lane+32;
        float v0 = lrelu(s1v + s2s[j0]) + feat_bias[i*64+j0];
        float v1 = lrelu(s1v + s2s[j1]) + feat_bias[i*64+j1];
        float m = fmaxf(v0,v1);
        #pragma unroll
        for(int off=16;off;off>>=1) m = fmaxf(m, __shfl_xor_sync(0xffffffffu, m, off));
        float e0 = __expf(v0-m), e1 = __expf(v1-m);
        float ssum = e0+e1;
        #pragma unroll
        for(int off=16;off;off>>=1) ssum += __shfl_xor_sync(0xffffffffu, ssum, off);
        float inv = 1.f/ssum;
        att[j0*64+i] = e0*inv;
        att[j1*64+i] = e1*inv;
    }
    __syncthreads();
    int i = t&63, wofs = t>>6;
    for(int wl=0; wl<16; wl++){
        int wA = (wl*2  )*4 + wofs;
        int wB = (wl*2+1)*4 + wofs;
        float accA = 0.f, accB = 0.f;
        #pragma unroll 8
        for(int j=0;j<64;j++){
            float av = att[j*64+i];
            accA += av*ys[wA*64+j];
            accB += av*ys[wB*64+j];
        }
        g_hfeat[(b*WW+wA)*KK + i] = sigm(accA);
        g_hfeat[(b*WW+wB)*KK + i] = sigm(accB);
    }
}

// ---------------- p,q via warp-level mma.sync tf32 ----------------
// grid (2=p/q, 64=batch). CTA: M=128 (timesteps) x N=128 (e) x K=64.
#define PQ_LD 68
#define PQ_SMEM_BYTES (2*128*PQ_LD*4)

__global__ __launch_bounds__(256,1) void k_pqmma(const float* __restrict__ tlw,
                                                 const float* __restrict__ tlb){
    extern __shared__ __align__(16) uint32_t psm[];
    uint32_t* sA = psm;                 // y rows [128][PQ_LD]
    uint32_t* sB = psm + 128*PQ_LD;     // W rows [128][PQ_LD]
    int t = threadIdx.x;                // 256
    int half = blockIdx.x;              // 0 -> p, 1 -> q
    int b = blockIdx.y;

    for(int i=t; i<128*16; i+=256){
        int row = i>>4, c4 = i&15;
        float4 v = *(const float4*)(g_y + (size_t)(b*WW+row)*KK + c4*4);
        uint32_t* d = sA + row*PQ_LD + c4*4;
        d[0]=to_tf32(v.x); d[1]=to_tf32(v.y); d[2]=to_tf32(v.z); d[3]=to_tf32(v.w);
    }
    for(int i=t; i<128*16; i+=256){
        int n = i>>4, c4 = i&15;
        float4 v = *(const float4*)(tlw + n*128 + half*64 + c4*4);
        uint32_t* d = sB + n*PQ_LD + c4*4;
        d[0]=to_tf32(v.x); d[1]=to_tf32(v.y); d[2]=to_tf32(v.z); d[3]=to_tf32(v.w);
    }
    __syncthreads();

    int w = t>>5, lane = t&31;
    int wm = (w>>1)*32, wn = (w&1)*64;
    int lr = lane>>2, lc = lane&3;

    float d[2][8][4];
    #pragma unroll
    for(int mt=0;mt<2;mt++)
        #pragma unroll
        for(int nt=0;nt<8;nt++)
            #pragma unroll
            for(int k=0;k<4;k++) d[mt][nt][k]=0.f;

    #pragma unroll
    for(int ks=0; ks<8; ks++){
        int k0 = ks*8;
        uint32_t a[2][4];
        #pragma unroll
        for(int mt=0;mt<2;mt++){
            const uint32_t* ab = sA + (wm + mt*16 + lr)*PQ_LD + k0 + lc;
            a[mt][0] = ab[0];
            a[mt][1] = ab[8*PQ_LD];
            a[mt][2] = ab[4];
            a[mt][3] = ab[8*PQ_LD + 4];
        }
        uint32_t bfr[8][2];
        #pragma unroll
        for(int nt=0;nt<8;nt++){
            const uint32_t* bb = sB + (wn + nt*8 + lr)*PQ_LD + k0 + lc;
            bfr[nt][0] = bb[0];
            bfr[nt][1] = bb[4];
        }
        #pragma unroll
        for(int mt=0;mt<2;mt++)
            #pragma unroll
            for(int nt=0;nt<8;nt++)
                mma_tf32_16x8x8(d[mt][nt][0], d[mt][nt][1], d[mt][nt][2], d[mt][nt][3],
                                a[mt][0], a[mt][1], a[mt][2], a[mt][3],
                                bfr[nt][0], bfr[nt][1]);
    }

    float* dstb = half==0 ? g_p : g_q;
    #pragma unroll
    for(int mt=0;mt<2;mt++){
        int row0 = wm + mt*16 + lr;
        float* dst0 = dstb + (size_t)(b*WW + row0)*ETD;
        float* dst1 = dstb + (size_t)(b*WW + row0 + 8)*ETD;
        #pragma unroll
        for(int nt=0;nt<8;nt++){
            int col = wn + nt*8 + 2*lc;
            float2 bv = (half==0) ? *(const float2*)(tlb + col) : make_float2(0.f,0.f);
            *(float2*)(dst0 + col) = make_float2(d[mt][nt][0]+bv.x, d[mt][nt][1]+bv.y);
            *(float2*)(dst1 + col) = make_float2(d[mt][nt][2]+bv.x, d[mt][nt][3]+bv.y);
        }
    }
}

// ---------------- temporal attention + h_temp (8 i's per block) ----------------
// Split: lrelu(v)*ta = 0.6ta*v + 0.4ta*|v|; linear part separates into
// pa[i] = sum_e 0.6ta*p[i,e] and qb[j] = sum_e 0.6ta*q[j,e]; inner loop only |.|
__global__ void k_temp(const float* __restrict__ temp_a, const float* __restrict__ temp_bias){
    int i0 = blockIdx.x*8; int b = blockIdx.y; int t = threadIdx.x; // 128 (= j = e)
    __shared__ __align__(16) float psst[8*128];
    __shared__ __align__(16) float ta6[128];
    __shared__ __align__(16) float ta4[128];
    __shared__ __align__(16) float atts[128*8];
    __shared__ float wr[8*4];
    __shared__ float hb[64*8];
    __shared__ float pa_s[8];
    {
        float tv = temp_a[t];
        ta6[t] = 0.6f*tv;
        ta4[t] = 0.4f*tv;
    }
    #pragma unroll
    for(int r=0;r<8;r++) psst[r*128+t] = g_p[(b*WW+i0+r)*ETD + t];
    __syncthreads();
    int lane = t&31, wd = t>>5;
    // pa[i] = sum_e ta6[e]*psst[i][e]  (thread t contributes e=t)
    #pragma unroll
    for(int i=0;i<8;i++){
        float v = ta6[t]*psst[i*128+t];
        #pragma unroll
        for(int off=16;off;off>>=1) v += __shfl_xor_sync(0xffffffffu, v, off);
        if(lane==0) wr[i*4+wd]=v;
    }
    __syncthreads();
    if(t<8) pa_s[t] = wr[t*4]+wr[t*4+1]+wr[t*4+2]+wr[t*4+3];
    __syncthreads();
    const float4* q4 = (const float4*)(g_q + (size_t)(b*WW+t)*ETD);
    float qb = 0.f;
    float ejb[8];
    #pragma unroll
    for(int i=0;i<8;i++) ejb[i]=0.f;
    for(int c=0;c<32;c++){
        float4 qv = q4[c];
        float4 a6 = *(const float4*)(ta6 + 4*c);
        float4 a4 = *(const float4*)(ta4 + 4*c);
        qb = fmaf(a6.x, qv.x, qb); qb = fmaf(a6.y, qv.y, qb);
        qb = fmaf(a6.z, qv.z, qb); qb = fmaf(a6.w, qv.w, qb);
        #pragma unroll
        for(int i=0;i<8;i++){
            const float4 pv = *(const float4*)(psst + i*128 + 4*c);
            ejb[i] = fmaf(a4.x, fabsf(pv.x+qv.x), ejb[i]);
            ejb[i] = fmaf(a4.y, fabsf(pv.y+qv.y), ejb[i]);
            ejb[i] = fmaf(a4.z, fabsf(pv.z+qv.z), ejb[i]);
            ejb[i] = fmaf(a4.w, fabsf(pv.w+qv.w), ejb[i]);
        }
    }
    float ej[8];
    #pragma unroll
    for(int i=0;i<8;i++)
        ej[i] = temp_bias[(i0+i)*WW + t] + pa_s[i] + qb + ejb[i];
    // softmax over j (=t)
    #pragma unroll
    for(int i=0;i<8;i++){
        float m = ej[i];
        #pragma unroll
        for(int off=16;off;off>>=1) m = fmaxf(m, __shfl_xor_sync(0xffffffffu, m, off));
        if(lane==0) wr[i*4+wd]=m;
    }
    __syncthreads();
    float mx[8];
    #pragma unroll
    for(int i=0;i<8;i++) mx[i] = fmaxf(fmaxf(wr[i*4],wr[i*4+1]), fmaxf(wr[i*4+2],wr[i*4+3]));
    __syncthreads();
    #pragma unroll
    for(int i=0;i<8;i++){
        float e = __expf(ej[i]-mx[i]); ej[i]=e;
        float ss = e;
        #pragma unroll
        for(int off=16;off;off>>=1) ss += __shfl_xor_sync(0xffffffffu, ss, off);
        if(lane==0) wr[i*4+wd]=ss;
    }
    __syncthreads();
    #pragma unroll
    for(int i=0;i<8;i++){
        float ss = wr[i*4]+wr[i*4+1]+wr[i*4+2]+wr[i*4+3];
        atts[t*8+i] = ej[i]/ss;
    }
    __syncthreads();
    int k = t&63, half = t>>6;
    float acc[8];
    #pragma unroll
    for(int i=0;i<8;i++) acc[i]=0.f;
    for(int j=0;j<64;j++){
        int jj = half*64+j;
        float yv = g_y[(b*WW+jj)*KK + k];
        const float4* a4 = (const float4*)(atts + jj*8);
        float4 aA = a4[0], aB = a4[1];
        acc[0]+=aA.x*yv; acc[1]+=aA.y*yv; acc[2]+=aA.z*yv; acc[3]+=aA.w*yv;
        acc[4]+=aB.x*yv; acc[5]+=aB.y*yv; acc[6]+=aB.z*yv; acc[7]+=aB.w*yv;
    }
    if(half==1){
        #pragma unroll
        for(int i=0;i<8;i++) hb[k*8+i]=acc[i];
    }
    __syncthreads();
    if(half==0){
        #pragma unroll
        for(int i=0;i<8;i++){
            float v = acc[i] + hb[k*8+i];
            g_htemp[(b*WW+i0+i)*KK + k] = sigm(v);
        }
    }
}

// ---------------- gi = Z @ wih^T + bih via warp-level mma.sync tf32 ----------------
#define GI_LD  196
#define GI_SMEM_BYTES (2*128*GI_LD*4)

__global__ __launch_bounds__(256,1) void k_gimma(const float* __restrict__ wih,
                                                 const float* __restrict__ bih){
    extern __shared__ __align__(16) uint32_t gsm[];
    uint32_t* sA = gsm;
    uint32_t* sB = gsm + 128*GI_LD;
    int t = threadIdx.x;
    int b  = blockIdx.y;
    int n0 = blockIdx.x * 128;

    for(int i=t; i<128*48; i+=256){
        int row = i/48, c4 = i - row*48;
        int kk = c4*4;
        int base = (b*WW+row)*KK;
        const float* src;
        if(kk<64)       src = g_y     + base + kk;
        else if(kk<128) src = g_hfeat + base + kk-64;
        else            src = g_htemp + base + kk-128;
        float4 v = *(const float4*)src;
        uint32_t* d = sA + row*GI_LD + kk;
        d[0]=to_tf32(v.x); d[1]=to_tf32(v.y); d[2]=to_tf32(v.z); d[3]=to_tf32(v.w);
    }
    for(int i=t; i<128*48; i+=256){
        int row = i/48, c4 = i - row*48;
        float4 v = *(const float4*)(wih + (size_t)(n0+row)*ZC + c4*4);
        uint32_t* d = sB + row*GI_LD + c4*4;
        d[0]=to_tf32(v.x); d[1]=to_tf32(v.y); d[2]=to_tf32(v.z); d[3]=to_tf32(v.w);
    }
    __syncthreads();

    int w = t>>5, lane = t&31;
    int wm = (w>>1)*32;
    int wn = (w&1)*64;
    int lr = lane>>2, lc = lane&3;

    float d[2][8][4];
    #pragma unroll
    for(int mt=0;mt<2;mt++)
        #pragma unroll
        for(int nt=0;nt<8;nt++)
            #pragma unroll
            for(int k=0;k<4;k++) d[mt][nt][k]=0.f;

    #pragma unroll 4
    for(int ks=0; ks<24; ks++){
        int k0 = ks*8;
        uint32_t a[2][4];
        #pragma unroll
        for(int mt=0;mt<2;mt++){
            const uint32_t* ab = sA + (wm + mt*16 + lr)*GI_LD + k0 + lc;
            a[mt][0] = ab[0];
            a[mt][1] = ab[8*GI_LD];
            a[mt][2] = ab[4];
            a[mt][3] = ab[8*GI_LD + 4];
        }
        uint32_t bfr[8][2];
        #pragma unroll
        for(int nt=0;nt<8;nt++){
            const uint32_t* bb = sB + (wn + nt*8 + lr)*GI_LD + k0 + lc;
            bfr[nt][0] = bb[0];
            bfr[nt][1] = bb[4];
        }
        #pragma unroll
        for(int mt=0;mt<2;mt++)
            #pragma unroll
            for(int nt=0;nt<8;nt++)
                mma_tf32_16x8x8(d[mt][nt][0], d[mt][nt][1], d[mt][nt][2], d[mt][nt][3],
                                a[mt][0], a[mt][1], a[mt][2], a[mt][3],
                                bfr[nt][0], bfr[nt][1]);
    }

    #pragma unroll
    for(int mt=0;mt<2;mt++){
        int row0 = wm + mt*16 + lr;
        float* dst0 = g_gi + (size_t)(b*WW + row0)*G3 + n0;
        float* dst1 = g_gi + (size_t)(b*WW + row0 + 8)*G3 + n0;
        #pragma unroll
        for(int nt=0;nt<8;nt++){
            int col = wn + nt*8 + 2*lc;
            float2 bv = *(const float2*)(bih + n0 + col);
            *(float2*)(dst0 + col) = make_float2(d[mt][nt][0]+bv.x, d[mt][nt][1]+bv.y);
            *(float2*)(dst1 + col) = make_float2(d[mt][nt][2]+bv.x, d[mt][nt][3]+bv.y);
        }
    }
}

// ---------------- GRU: 32 clusters x 4 slice-CTAs (R8 bulk exchange) ----------------
__global__ __launch_bounds__(256,1) __cluster_dims__(4,1,1) void k_gru(const float* __restrict__ bhh){
    int t = threadIdx.x;       // 256
    int p = blockIdx.x >> 2;   // batch-pair group
    uint32_t s;                // slice = rank in cluster
    asm("mov.u32 %0, %%cluster_ctarank;" : "=r"(s));
    __shared__ __align__(16) unsigned long long hsu[2][128][2];  // [buf][jp][b]
    __shared__ float part[4][3][2][64];                          // [hq][gate][b][u]
    __shared__ __align__(16) float stg[2][32][2][2];             // [buf][jl2][b][par]
    __shared__ __align__(8)  unsigned long long mbar[2];
    uint32_t mb0 = smem_u32(&mbar[0]), mb1 = smem_u32(&mbar[1]);
    for(int i=t;i<512;i+=256){ ((unsigned long long*)hsu)[i] = 0ull; }
    if(t==0){ mbar_init(mb0,1); mbar_init(mb1,1); }
    __syncthreads();
    asm volatile("barrier.cluster.arrive.aligned;" ::: "memory");
    asm volatile("barrier.cluster.wait.aligned;" ::: "memory");

    int u = t&63, hq = t>>6;
    const unsigned long long* wsrc = ((const unsigned long long*)g_whhR) + (size_t)s*96*256 + t;
    unsigned long long wreg[64];
    #pragma unroll
    for(int i=0;i<64;i++) wreg[i] = wsrc[(size_t)i*256];
    const unsigned long long* wn = wsrc + (size_t)64*256;   // gate n base

    int gu = t&63, gb = (t>>6)&1;
    float bhr=0.f, bhz=0.f, bhn=0.f;
    if(t<128){
        bhr = bhh[      64*s+gu];
        bhz = bhh[256 + 64*s+gu];
        bhn = bhh[512 + 64*s+gu];
    }
    const float* gib0 = g_gi + (size_t)(2*p+gb)*WW*G3 + s*64 + gu;
    float pfr=0.f, pfz=0.f, pfn=0.f;
    if(t<128){ pfr=__ldcg(gib0); pfz=__ldcg(gib0+256); pfn=__ldcg(gib0+512); }
    int ph0=0, ph1=0;

    for(int step=0; step<WW; step++){
        int cb = step&1, nb = cb^1;
        if(step>0){
            if(cb==0){ mbar_wait(mb0, ph0); ph0^=1; }
            else     { mbar_wait(mb1, ph1); ph1^=1; }
        }
        if(t==0 && step<127) mbar_expect(nb==0? mb0 : mb1, 2048);

        unsigned long long a00=0ull,a01=0ull,a10=0ull,a11=0ull,a20=0ull,a21=0ull;
        const ulonglong2* hp = ((const ulonglong2*)hsu[cb]) + hq*32;
        #pragma unroll
        for(int jl=0;jl<32;jl++){
            ulonglong2 hv = hp[jl];
            unsigned long long wnl = __ldg(wn + (size_t)jl*256);
            fma2(a00, wreg[jl],    hv.x); fma2(a01, wreg[jl],    hv.y);
            fma2(a10, wreg[32+jl], hv.x); fma2(a11, wreg[32+jl], hv.y);
            fma2(a20, wnl,         hv.x); fma2(a21, wnl,         hv.y);
        }
        part[hq][0][0][u]=ull_sum(a00); part[hq][0][1][u]=ull_sum(a01);
        part[hq][1][0][u]=ull_sum(a10); part[hq][1][1][u]=ull_sum(a11);
        part[hq][2][0][u]=ull_sum(a20); part[hq][2][1][u]=ull_sum(a21);
        __syncthreads();
        if(t < 128){
            float gr=pfr, gz=pfz, gn=pfn;
            if(step<127){
                const float* gnx = gib0 + (size_t)(step+1)*G3;
                pfr=__ldcg(gnx); pfz=__ldcg(gnx+256); pfn=__ldcg(gnx+512);
            }
            float ghr = bhr + ((part[0][0][gb][gu]+part[1][0][gb][gu])+(part[2][0][gb][gu]+part[3][0][gb][gu]));
            float ghz = bhz + ((part[0][1][gb][gu]+part[1][1][gb][gu])+(part[2][1][gb][gu]+part[3][1][gb][gu]));
            float ghn = bhn + ((part[0][2][gb][gu]+part[1][2][gb][gu])+(part[2][2][gb][gu]+part[3][2][gb][gu]));
            float hold = ((const float*)hsu[cb])[ (((32*(int)s + (gu>>1))*2) + gb)*2 + (gu&1) ];
            float r  = sigm(gr+ghr);
            float zg = sigm(gz+ghz);
            float n  = tanh_fast(gn + r*ghn);
            float hnew = n + zg*(hold - n);
            if(step==127) g_h[(size_t)(2*p+gb)*HH + 64*s + gu] = hnew;
            else          stg[cb][gu>>1][gb][gu&1] = hnew;
        }
        __syncthreads();
        if(t<4 && step<127){
            asm volatile("fence.proxy.async.shared::cta;" ::: "memory");
            uint32_t src  = smem_u32(&stg[cb][0][0][0]);
            uint32_t dstl = smem_u32(&hsu[nb][32*(int)s][0]);
            uint32_t mbn  = nb==0 ? mb0 : mb1;
            uint32_t tr = (uint32_t)t;
            uint32_t rb = mapa_u32(mbn, tr);
            dsmem_bulk(mapa_u32(dstl, tr), src, 512, rb);
        }
    }
}

// ---------------- MLP head ----------------
__global__ void k_mlp(const float* __restrict__ b0, const float* __restrict__ b1,
                      const float* __restrict__ b2, const float* __restrict__ b3,
                      float* __restrict__ out){
    int b = blockIdx.x; int t = threadIdx.x; // 256
    __shared__ float va[FHD], vb[FHD];
    va[t] = g_h[b*HH + t];
    __syncthreads();
    float p0=0.f,p1=0.f,p2=0.f,p3=0.f;
    #pragma unroll 4
    for(int j=0;j<HH;j+=4){
        p0 += va[j  ]*g_fc0T[(j  )*FHD + t];
        p1 += va[j+1]*g_fc0T[(j+1)*FHD + t];
        p2 += va[j+2]*g_fc0T[(j+2)*FHD + t];
        p3 += va[j+3]*g_fc0T[(j+3)*FHD + t];
    }
    vb[t] = fmaxf(b0[t] + ((p0+p1)+(p2+p3)), 0.f);
    __syncthreads();
    p0=p1=p2=p3=0.f;
    #pragma unroll 4
    for(int j=0;j<FHD;j+=4){
        p0 += vb[j  ]*g_fc1T[(j  )*FHD + t];
        p1 += vb[j+1]*g_fc1T[(j+1)*FHD + t];
        p2 += vb[j+2]*g_fc1T[(j+2)*FHD + t];
        p3 += vb[j+3]*g_fc1T[(j+3)*FHD + t];
    }
    va[t] = fmaxf(b1[t] + ((p0+p1)+(p2+p3)), 0.f);
    __syncthreads();
    p0=p1=p2=p3=0.f;
    #pragma unroll 4
    for(int j=0;j<FHD;j+=4){
        p0 += va[j  ]*g_fc2T[(j  )*FHD + t];
        p1 += va[j+1]*g_fc2T[(j+1)*FHD + t];
        p2 += va[j+2]*g_fc2T[(j+2)*FHD + t];
        p3 += va[j+3]*g_fc2T[(j+3)*FHD + t];
    }
    vb[t] = fmaxf(b2[t] + ((p0+p1)+(p2+p3)), 0.f);
    __syncthreads();
    if(t < 64){
        p0=p1=p2=p3=0.f;
        #pragma unroll 4
        for(int j=0;j<FHD;j+=4){
            p0 += vb[j  ]*g_fc3T[(j  )*64 + t];
            p1 += vb[j+1]*g_fc3T[(j+1)*64 + t];
            p2 += vb[j+2]*g_fc3T[(j+2)*64 + t];
            p3 += vb[j+3]*g_fc3T[(j+3)*64 + t];
        }
        out[b*64 + t] = b3[t] + ((p0+p1)+(p2+p3));
    }
}

// ---------------- launch ----------------
extern "C" void kernel_launch(void* const* d_in, const int* in_sizes, int n_in,
                              void* d_out, int out_size){
    const float* x        = (const float*)d_in[0];
    const float* conv_w   = (const float*)d_in[1];
    const float* conv_b   = (const float*)d_in[2];
    const float* flw      = (const float*)d_in[3];
    const float* flb      = (const float*)d_in[4];
    const float* fa       = (const float*)d_in[5];
    const float* fbias    = (const float*)d_in[6];
    const float* tlw      = (const float*)d_in[7];
    const float* tlb      = (const float*)d_in[8];
    const float* ta       = (const float*)d_in[9];
    const float* tbias    = (const float*)d_in[10];
    const float* wih      = (const float*)d_in[11];
    const float* whh      = (const float*)d_in[12];
    const float* bih      = (const float*)d_in[13];
    const float* bhh      = (const float*)d_in[14];
    const float* fc0_w    = (const float*)d_in[15];
    const float* fc0_b    = (const float*)d_in[16];
    const float* fc1_w    = (const float*)d_in[17];
    const float* fc1_b    = (const float*)d_in[18];
    const float* fc2_w    = (const float*)d_in[19];
    const float* fc2_b    = (const float*)d_in[20];
    const float* fc3_w    = (const float*)d_in[21];
    const float* fc3_b    = (const float*)d_in[22];
    float* out = (float*)d_out;

    static int smem_set = 0;
    if(!smem_set){
        cudaFuncSetAttribute(k_gimma, cudaFuncAttributeMaxDynamicSharedMemorySize, GI_SMEM_BYTES);
        cudaFuncSetAttribute(k_pqmma, cudaFuncAttributeMaxDynamicSharedMemorySize, PQ_SMEM_BYTES);
        smem_set = 1;
    }

    k_prep<<<2353, 256>>>(conv_w, tlw, whh, fc0_w, fc1_w, fc2_w, fc3_w, flw, flb, fa);
    k_conv<<<dim3(8, 64), 128>>>(x, conv_b);
    k_feat<<<64, 256>>>(fbias);
    k_pqmma<<<dim3(2, 64), 256, PQ_SMEM_BYTES>>>(tlw, tlb);
    k_temp<<<dim3(16, 64), 128>>>(ta, tbias);
    k_gimma<<<dim3(6, 64), 256, GI_SMEM_BYTES>>>(wih, bih);
    k_gru<<<128, 256>>>(bhh);
    k_mlp<<<64, 256>>>(fc0_b, fc1_b, fc2_b, fc3_b, out);
}

// round 16
// speedup vs baseline: 1.0373x; 1.0373x over previous
#include <cuda_runtime.h>
#include <math.h>
#include <stdint.h>

#define BB  64
#define WW  128
#define KK  64
#define KSZ 7
#define EFD 128
#define ETD 128
#define HH  256
#define FHD 256
#define G3  768   // 3*H
#define ZC  192   // 3*K

// ---------------- scratch (static device globals; no runtime alloc) ----------------
__device__ __align__(16) float g_y[BB*WW*KK];
__device__ __align__(16) float g_hfeat[BB*WW*KK];
__device__ __align__(16) float g_htemp[BB*WW*KK];
__device__ __align__(16) float g_p[BB*WW*ETD];
__device__ __align__(16) float g_q[BB*WW*ETD];
__device__ __align__(16) float g_gi[BB*WW*G3];
__device__ float g_h[BB*HH];
__device__ __align__(16) float g_cwT[KSZ*KK*KK];   // [s][i][k]
__device__ __align__(16) float g_tlwT[ETD*ETD];    // [c][e]
__device__ __align__(16) float g_whhR[4*96*256*2]; // [slice][i=g*32+jl][col=hq*64+u][par]
__device__ __align__(16) float g_fc0T[FHD*FHD];
__device__ __align__(16) float g_fc1T[FHD*FHD];
__device__ __align__(16) float g_fc2T[FHD*FHD];
__device__ __align__(16) float g_fc3T[FHD*KK];
__device__ float g_u1[WW];
__device__ float g_u2[WW];
__device__ float g_c12[2];

__device__ __forceinline__ float sigm(float x){ return 1.f/(1.f+__expf(-x)); }
__device__ __forceinline__ float tanh_fast(float x){
    float e2 = __expf(2.f*x);
    return 1.f - 2.f/(e2+1.f);
}
__device__ __forceinline__ float lrelu(float v){ return fmaxf(v, 0.2f*v); } // ALPHA=0.2<1

__device__ __forceinline__ uint32_t smem_u32(const void* p){
    uint32_t a;
    asm("{ .reg .u64 t0; cvta.to.shared.u64 t0, %1; cvt.u32.u64 %0, t0; }" : "=r"(a) : "l"(p));
    return a;
}
__device__ __forceinline__ void fma2(unsigned long long& a, unsigned long long w, unsigned long long h){
    asm("fma.rn.f32x2 %0, %1, %2, %0;" : "+l"(a) : "l"(w), "l"(h));
}
__device__ __forceinline__ float ull_sum(unsigned long long v){
    unsigned lo, hi;
    asm("mov.b64 {%0,%1}, %2;" : "=r"(lo), "=r"(hi) : "l"(v));
    return __uint_as_float(lo) + __uint_as_float(hi);
}
__device__ __forceinline__ unsigned long long bcast2(float v){
    unsigned long long r;
    asm("mov.b64 %0, {%1, %1};" : "=l"(r) : "r"(__float_as_uint(v)));
    return r;
}
__device__ __forceinline__ void mbar_init(uint32_t mb, uint32_t cnt){
    asm volatile("mbarrier.init.shared.b64 [%0], %1;" :: "r"(mb), "r"(cnt) : "memory");
}
__device__ __forceinline__ void mbar_expect(uint32_t mb, uint32_t tx){
    asm volatile("mbarrier.arrive.expect_tx.shared.b64 _, [%0], %1;" :: "r"(mb), "r"(tx) : "memory");
}
__device__ __forceinline__ void mbar_wait(uint32_t mb, int parity){
    asm volatile(
        "{\n\t.reg .pred P1;\n\t"
        "WL_%=:\n\t"
        "mbarrier.try_wait.parity.acquire.cta.shared::cta.b64 P1, [%0], %1, 0x989680;\n\t"
        "@P1 bra.uni WD_%=;\n\t"
        "bra.uni WL_%=;\n\t"
        "WD_%=:\n\t}"
        :: "r"(mb), "r"(parity) : "memory");
}
__device__ __forceinline__ uint32_t mapa_u32(uint32_t a, uint32_t rank){
    uint32_t r;
    asm("mapa.shared::cluster.u32 %0, %1, %2;" : "=r"(r) : "r"(a), "r"(rank));
    return r;
}
__device__ __forceinline__ void dsmem_bulk(uint32_t dst, uint32_t src, uint32_t bytes, uint32_t rbar){
    asm volatile("cp.async.bulk.shared::cluster.shared::cta.mbarrier::complete_tx::bytes [%0], [%1], %2, [%3];"
                 :: "r"(dst), "r"(src), "r"(bytes), "r"(rbar) : "memory");
}
__device__ __forceinline__ uint32_t to_tf32(float v){
    uint32_t r;
    asm("cvt.rna.tf32.f32 %0, %1;" : "=r"(r) : "f"(v));
    return r;
}
__device__ __forceinline__ void mma_tf32_16x8x8(float& d0, float& d1, float& d2, float& d3,
                                                uint32_t a0, uint32_t a1, uint32_t a2, uint32_t a3,
                                                uint32_t b0, uint32_t b1){
    asm volatile("mma.sync.aligned.m16n8k8.row.col.f32.tf32.tf32.f32 "
                 "{%0,%1,%2,%3}, {%4,%5,%6,%7}, {%8,%9}, {%0,%1,%2,%3};"
                 : "+f"(d0), "+f"(d1), "+f"(d2), "+f"(d3)
                 : "r"(a0), "r"(a1), "r"(a2), "r"(a3), "r"(b0), "r"(b1));
}

// ---------------- weight reshapes / transposes + u1/u2/c12 ----------------
__global__ void k_prep(const float* __restrict__ conv_w, const float* __restrict__ tlw,
                       const float* __restrict__ whh,
                       const float* __restrict__ fc0, const float* __restrict__ fc1,
                       const float* __restrict__ fc2, const float* __restrict__ fc3,
                       const float* __restrict__ flw, const float* __restrict__ flb,
                       const float* __restrict__ fa){
    int idx = blockIdx.x*blockDim.x + threadIdx.x;
    if(idx < 28672){
        int k = idx/448; int rem = idx - k*448; int i = rem/7; int s = rem - i*7;
        g_cwT[(s*64+i)*64 + k] = conv_w[idx];
        return;
    }
    idx -= 28672;
    if(idx < 16384){
        int e = idx>>7, c = idx&127;
        g_tlwT[c*128 + e] = tlw[idx];
        return;
    }
    idx -= 16384;
    if(idx < 196608){
        int o = idx>>8, j = idx&255;
        int g = o>>8;
        int ou = o&255;
        int s = ou>>6, u = ou&63;
        int hq = j>>6;
        int jl = (j&63)>>1;
        int par = j&1;
        int d = (s*96 + g*32 + jl)*256 + (hq*64 + u);
        g_whhR[d*2 + par] = whh[idx];
        return;
    }
    idx -= 196608;
    if(idx < 65536){ int o = idx>>8, j = idx&255; g_fc0T[j*256+o] = fc0[idx]; return; }
    idx -= 65536;
    if(idx < 65536){ int o = idx>>8, j = idx&255; g_fc1T[j*256+o] = fc1[idx]; return; }
    idx -= 65536;
    if(idx < 65536){ int o = idx>>8, j = idx&255; g_fc2T[j*256+o] = fc2[idx]; return; }
    idx -= 65536;
    if(idx < 16384){ int o = idx>>8, j = idx&255; g_fc3T[j*64+o] = fc3[idx]; return; }
    idx -= 16384;
    if(idx < 128){
        float a1=0.f, a2=0.f;
        for(int e=0;e<EFD;e++){ float w = flw[e*WW + idx]; a1 += w*fa[e]; a2 += w*fa[EFD+e]; }
        g_u1[idx]=a1; g_u2[idx]=a2;
        return;
    }
    if(idx==128){ float c=0.f; for(int e=0;e<EFD;e++) c += flb[e]*fa[e];     g_c12[0]=c; return; }
    if(idx==129){ float c=0.f; for(int e=0;e<EFD;e++) c += flb[e]*fa[EFD+e]; g_c12[1]=c; return; }
}

// ---------------- conv1d (pad=3) + relu -> y[b,w,k] ; f32x2 over k-pairs ----------------
__global__ void k_conv(const float* __restrict__ x, const float* __restrict__ conv_b){
    int b = blockIdx.y; int w0 = blockIdx.x*16;
    int t = threadIdx.x; // 128
    int kp = t&31, wq = t>>5;
    __shared__ float xs[22*64];
    for(int i=t; i<22*64; i+=128){
        int row = w0-3+(i>>6);
        xs[i] = (row>=0 && row<WW) ? x[(b*WW+row)*KK + (i&63)] : 0.f;
    }
    __syncthreads();
    unsigned long long acc[4];
    {
        float2 b2 = *(const float2*)(conv_b + 2*kp);
        unsigned long long bb;
        asm("mov.b64 %0, {%1, %2};" : "=l"(bb) : "r"(__float_as_uint(b2.x)), "r"(__float_as_uint(b2.y)));
        #pragma unroll
        for(int r=0;r<4;r++) acc[r]=bb;
    }
    #pragma unroll
    for(int s=0;s<KSZ;s++){
        #pragma unroll 8
        for(int i=0;i<KK;i++){
            unsigned long long cw2 = *(const unsigned long long*)(g_cwT + (s*64+i)*64 + 2*kp);
            #pragma unroll
            for(int r=0;r<4;r++){
                unsigned long long xx = bcast2(xs[(wq*4+r+s)*64 + i]);
                fma2(acc[r], cw2, xx);
            }
        }
    }
    #pragma unroll
    for(int r=0;r<4;r++){
        unsigned lo, hi;
        asm("mov.b64 {%0,%1}, %2;" : "=r"(lo), "=r"(hi) : "l"(acc[r]));
        float2 o;
        o.x = fmaxf(__uint_as_float(lo), 0.f);
        o.y = fmaxf(__uint_as_float(hi), 0.f);
        *(float2*)(g_y + (size_t)(b*WW + w0 + wq*4 + r)*KK + 2*kp) = o;
    }
}

// ---------------- feature attention + h_feat (s1/s2 fused in) ----------------
__global__ __launch_bounds__(256) void k_feat(const float* __restrict__ feat_bias){
    int b = blockIdx.x; int t = threadIdx.x; // 256
    __shared__ float ys[WW*KK];
    __shared__ float att[KK*KK];
    __shared__ float u1s[WW], u2s[WW];
    __shared__ float r1[256], r2[256];
    __shared__ float s1s[64], s2s[64];
    if(t<128){ u1s[t]=g_u1[t]; u2s[t]=g_u2[t]; }
    for(int it=0; it<32; it++){ int idx = it*256+t; ys[idx] = g_y[b*WW*KK + idx]; }
    __syncthreads();
    {
        int k = t&63, q = t>>6;
        float a1=0.f, a2=0.f;
        #pragma unroll 8
        for(int w=q*32; w<q*32+32; w++){
            float yv = ys[w*64+k];
            a1 += yv*u1s[w]; a2 += yv*u2s[w];
        }
        r1[t]=a1; r2[t]=a2;
    }
    __syncthreads();
    if(t<64){
        s1s[t] = r1[t]+r1[t+64]+r1[t+128]+r1[t+192] + g_c12[0];
        s2s[t] = r2[t]+r2[t+64]+r2[t+128]+r2[t+192] + g_c12[1];
    }
    __syncthreads();
    int lane = t&31, wd = t>>5;
    #pragma unroll
    for(int r=0;r<8;r++){
        int i = wd*8 + r;
        float s1v = s1s[i];
        int j0 = lane, j1 = lane+32;
        float v0 = lrelu(s1v + s2s[j0]) + feat_bias[i*64+j0];
        float v1 = lrelu(s1v + s2s[j1]) + feat_bias[i*64+j1];
        float m = fmaxf(v0,v1);
        #pragma unroll
        for(int off=16;off;off>>=1) m = fmaxf(m, __shfl_xor_sync(0xffffffffu, m, off));
        float e0 = __expf(v0-m), e1 = __expf(v1-m);
        float ssum = e0+e1;
        #pragma unroll
        for(int off=16;off;off>>=1) ssum += __shfl_xor_sync(0xffffffffu, ssum, off);
        float inv = 1.f/ssum;
        att[j0*64+i] = e0*inv;
        att[j1*64+i] = e1*inv;
    }
    __syncthreads();
    int i = t&63, wofs = t>>6;
    for(int wl=0; wl<16; wl++){
        int wA = (wl*2  )*4 + wofs;
        int wB = (wl*2+1)*4 + wofs;
        float accA = 0.f, accB = 0.f;
        #pragma unroll 8
        for(int j=0;j<64;j++){
            float av = att[j*64+i];
            accA += av*ys[wA*64+j];
            accB += av*ys[wB*64+j];
        }
        g_hfeat[(b*WW+wA)*KK + i] = sigm(accA);
        g_hfeat[(b*WW+wB)*KK + i] = sigm(accB);
    }
}

// ---------------- p,q via warp-level mma.sync tf32 (measured 13.7us) ----------------
#define PQ_LD 68
#define PQ_SMEM_BYTES (2*128*PQ_LD*4)

__global__ __launch_bounds__(256,1) void k_pqmma(const float* __restrict__ tlw,
                                                 const float* __restrict__ tlb){
    extern __shared__ __align__(16) uint32_t psm[];
    uint32_t* sA = psm;                 // y rows [128][PQ_LD]
    uint32_t* sB = psm + 128*PQ_LD;     // W rows [128][PQ_LD]
    int t = threadIdx.x;                // 256
    int half = blockIdx.x;              // 0 -> p, 1 -> q
    int b = blockIdx.y;

    for(int i=t; i<128*16; i+=256){
        int row = i>>4, c4 = i&15;
        float4 v = *(const float4*)(g_y + (size_t)(b*WW+row)*KK + c4*4);
        uint32_t* d = sA + row*PQ_LD + c4*4;
        d[0]=to_tf32(v.x); d[1]=to_tf32(v.y); d[2]=to_tf32(v.z); d[3]=to_tf32(v.w);
    }
    for(int i=t; i<128*16; i+=256){
        int n = i>>4, c4 = i&15;
        float4 v = *(const float4*)(tlw + n*128 + half*64 + c4*4);
        uint32_t* d = sB + n*PQ_LD + c4*4;
        d[0]=to_tf32(v.x); d[1]=to_tf32(v.y); d[2]=to_tf32(v.z); d[3]=to_tf32(v.w);
    }
    __syncthreads();

    int w = t>>5, lane = t&31;
    int wm = (w>>1)*32, wn = (w&1)*64;
    int lr = lane>>2, lc = lane&3;

    float d[2][8][4];
    #pragma unroll
    for(int mt=0;mt<2;mt++)
        #pragma unroll
        for(int nt=0;nt<8;nt++)
            #pragma unroll
            for(int k=0;k<4;k++) d[mt][nt][k]=0.f;

    #pragma unroll
    for(int ks=0; ks<8; ks++){
        int k0 = ks*8;
        uint32_t a[2][4];
        #pragma unroll
        for(int mt=0;mt<2;mt++){
            const uint32_t* ab = sA + (wm + mt*16 + lr)*PQ_LD + k0 + lc;
            a[mt][0] = ab[0];
            a[mt][1] = ab[8*PQ_LD];
            a[mt][2] = ab[4];
            a[mt][3] = ab[8*PQ_LD + 4];
        }
        uint32_t bfr[8][2];
        #pragma unroll
        for(int nt=0;nt<8;nt++){
            const uint32_t* bb = sB + (wn + nt*8 + lr)*PQ_LD + k0 + lc;
            bfr[nt][0] = bb[0];
            bfr[nt][1] = bb[4];
        }
        #pragma unroll
        for(int mt=0;mt<2;mt++)
            #pragma unroll
            for(int nt=0;nt<8;nt++)
                mma_tf32_16x8x8(d[mt][nt][0], d[mt][nt][1], d[mt][nt][2], d[mt][nt][3],
                                a[mt][0], a[mt][1], a[mt][2], a[mt][3],
                                bfr[nt][0], bfr[nt][1]);
    }

    float* dstb = half==0 ? g_p : g_q;
    #pragma unroll
    for(int mt=0;mt<2;mt++){
        int row0 = wm + mt*16 + lr;
        float* dst0 = dstb + (size_t)(b*WW + row0)*ETD;
        float* dst1 = dstb + (size_t)(b*WW + row0 + 8)*ETD;
        #pragma unroll
        for(int nt=0;nt<8;nt++){
            int col = wn + nt*8 + 2*lc;
            float2 bv = (half==0) ? *(const float2*)(tlb + col) : make_float2(0.f,0.f);
            *(float2*)(dst0 + col) = make_float2(d[mt][nt][0]+bv.x, d[mt][nt][1]+bv.y);
            *(float2*)(dst1 + col) = make_float2(d[mt][nt][2]+bv.x, d[mt][nt][3]+bv.y);
        }
    }
}

// ---------------- temporal attention + h_temp (16 i's per block; R13 3-instr inner) ----------------
__global__ __launch_bounds__(128) void k_temp(const float* __restrict__ temp_a, const float* __restrict__ temp_bias){
    int i0 = blockIdx.x*16; int b = blockIdx.y; int t = threadIdx.x; // 128 (= j)
    __shared__ __align__(16) float psst[16*128];
    __shared__ __align__(16) float ta6[128];
    __shared__ __align__(16) float ta4[128];
    __shared__ __align__(16) float atts[128*16];
    __shared__ float wr[16*4];
    __shared__ float hb[64*16];
    {
        float tv = temp_a[t];
        ta6[t] = 0.6f*tv;
        ta4[t] = 0.4f*tv;
    }
    #pragma unroll
    for(int r=0;r<16;r++) psst[r*128+t] = g_p[(b*WW+i0+r)*ETD + t];
    __syncthreads();
    const float4* q4 = (const float4*)(g_q + (size_t)(b*WW+t)*ETD);
    float eja[16], ejb[16];
    #pragma unroll
    for(int i=0;i<16;i++){ eja[i] = temp_bias[(i0+i)*WW + t]; ejb[i]=0.f; }
    for(int c=0;c<32;c++){
        float4 qv = q4[c];
        float4 a6 = *(const float4*)(ta6 + 4*c);
        float4 a4 = *(const float4*)(ta4 + 4*c);
        #pragma unroll
        for(int i=0;i<16;i++){
            float4 pv = *(const float4*)(psst + i*128 + 4*c);
            float v0 = pv.x+qv.x, v1 = pv.y+qv.y, v2 = pv.z+qv.z, v3 = pv.w+qv.w;
            eja[i] = fmaf(a6.x, v0, eja[i]); ejb[i] = fmaf(a4.x, fabsf(v0), ejb[i]);
            eja[i] = fmaf(a6.y, v1, eja[i]); ejb[i] = fmaf(a4.y, fabsf(v1), ejb[i]);
            eja[i] = fmaf(a6.z, v2, eja[i]); ejb[i] = fmaf(a4.z, fabsf(v2), ejb[i]);
            eja[i] = fmaf(a6.w, v3, eja[i]); ejb[i] = fmaf(a4.w, fabsf(v3), ejb[i]);
        }
    }
    float ej[16];
    #pragma unroll
    for(int i=0;i<16;i++) ej[i] = eja[i]+ejb[i];
    int lane = t&31, wd = t>>5;
    #pragma unroll
    for(int i=0;i<16;i++){
        float m = ej[i];
        #pragma unroll
        for(int off=16;off;off>>=1) m = fmaxf(m, __shfl_xor_sync(0xffffffffu, m, off));
        if(lane==0) wr[i*4+wd]=m;
    }
    __syncthreads();
    float mx[16];
    #pragma unroll
    for(int i=0;i<16;i++) mx[i] = fmaxf(fmaxf(wr[i*4],wr[i*4+1]), fmaxf(wr[i*4+2],wr[i*4+3]));
    __syncthreads();
    #pragma unroll
    for(int i=0;i<16;i++){
        float e = __expf(ej[i]-mx[i]); ej[i]=e;
        float ss = e;
        #pragma unroll
        for(int off=16;off;off>>=1) ss += __shfl_xor_sync(0xffffffffu, ss, off);
        if(lane==0) wr[i*4+wd]=ss;
    }
    __syncthreads();
    #pragma unroll
    for(int i=0;i<16;i++){
        float ss = wr[i*4]+wr[i*4+1]+wr[i*4+2]+wr[i*4+3];
        atts[t*16+i] = ej[i]/ss;
    }
    __syncthreads();
    int k = t&63, half = t>>6;
    float acc[16];
    #pragma unroll
    for(int i=0;i<16;i++) acc[i]=0.f;
    for(int j=0;j<64;j++){
        int jj = half*64+j;
        float yv = g_y[(b*WW+jj)*KK + k];
        const float4* a4 = (const float4*)(atts + jj*16);
        #pragma unroll
        for(int c4=0;c4<4;c4++){
            float4 av = a4[c4];
            acc[c4*4+0]+=av.x*yv; acc[c4*4+1]+=av.y*yv;
            acc[c4*4+2]+=av.z*yv; acc[c4*4+3]+=av.w*yv;
        }
    }
    if(half==1){
        #pragma unroll
        for(int i=0;i<16;i++) hb[k*16+i]=acc[i];
    }
    __syncthreads();
    if(half==0){
        #pragma unroll
        for(int i=0;i<16;i++){
            float v = acc[i] + hb[k*16+i];
            g_htemp[(b*WW+i0+i)*KK + k] = sigm(v);
        }
    }
}

// ---------------- gi = Z @ wih^T + bih via warp-level mma.sync tf32 ----------------
#define GI_LD  196
#define GI_SMEM_BYTES (2*128*GI_LD*4)

__global__ __launch_bounds__(256,1) void k_gimma(const float* __restrict__ wih,
                                                 const float* __restrict__ bih){
    extern __shared__ __align__(16) uint32_t gsm[];
    uint32_t* sA = gsm;
    uint32_t* sB = gsm + 128*GI_LD;
    int t = threadIdx.x;
    int b  = blockIdx.y;
    int n0 = blockIdx.x * 128;

    for(int i=t; i<128*48; i+=256){
        int row = i/48, c4 = i - row*48;
        int kk = c4*4;
        int base = (b*WW+row)*KK;
        const float* src;
        if(kk<64)       src = g_y     + base + kk;
        else if(kk<128) src = g_hfeat + base + kk-64;
        else            src = g_htemp + base + kk-128;
        float4 v = *(const float4*)src;
        uint32_t* d = sA + row*GI_LD + kk;
        d[0]=to_tf32(v.x); d[1]=to_tf32(v.y); d[2]=to_tf32(v.z); d[3]=to_tf32(v.w);
    }
    for(int i=t; i<128*48; i+=256){
        int row = i/48, c4 = i - row*48;
        float4 v = *(const float4*)(wih + (size_t)(n0+row)*ZC + c4*4);
        uint32_t* d = sB + row*GI_LD + c4*4;
        d[0]=to_tf32(v.x); d[1]=to_tf32(v.y); d[2]=to_tf32(v.z); d[3]=to_tf32(v.w);
    }
    __syncthreads();

    int w = t>>5, lane = t&31;
    int wm = (w>>1)*32;
    int wn = (w&1)*64;
    int lr = lane>>2, lc = lane&3;

    float d[2][8][4];
    #pragma unroll
    for(int mt=0;mt<2;mt++)
        #pragma unroll
        for(int nt=0;nt<8;nt++)
            #pragma unroll
            for(int k=0;k<4;k++) d[mt][nt][k]=0.f;

    #pragma unroll 4
    for(int ks=0; ks<24; ks++){
        int k0 = ks*8;
        uint32_t a[2][4];
        #pragma unroll
        for(int mt=0;mt<2;mt++){
            const uint32_t* ab = sA + (wm + mt*16 + lr)*GI_LD + k0 + lc;
            a[mt][0] = ab[0];
            a[mt][1] = ab[8*GI_LD];
            a[mt][2] = ab[4];
            a[mt][3] = ab[8*GI_LD + 4];
        }
        uint32_t bfr[8][2];
        #pragma unroll
        for(int nt=0;nt<8;nt++){
            const uint32_t* bb = sB + (wn + nt*8 + lr)*GI_LD + k0 + lc;
            bfr[nt][0] = bb[0];
            bfr[nt][1] = bb[4];
        }
        #pragma unroll
        for(int mt=0;mt<2;mt++)
            #pragma unroll
            for(int nt=0;nt<8;nt++)
                mma_tf32_16x8x8(d[mt][nt][0], d[mt][nt][1], d[mt][nt][2], d[mt][nt][3],
                                a[mt][0], a[mt][1], a[mt][2], a[mt][3],
                                bfr[nt][0], bfr[nt][1]);
    }

    #pragma unroll
    for(int mt=0;mt<2;mt++){
        int row0 = wm + mt*16 + lr;
        float* dst0 = g_gi + (size_t)(b*WW + row0)*G3 + n0;
        float* dst1 = g_gi + (size_t)(b*WW + row0 + 8)*G3 + n0;
        #pragma unroll
        for(int nt=0;nt<8;nt++){
            int col = wn + nt*8 + 2*lc;
            float2 bv = *(const float2*)(bih + n0 + col);
            *(float2*)(dst0 + col) = make_float2(d[mt][nt][0]+bv.x, d[mt][nt][1]+bv.y);
            *(float2*)(dst1 + col) = make_float2(d[mt][nt][2]+bv.x, d[mt][nt][3]+bv.y);
        }
    }
}

// ---------------- GRU: 32 clusters x 4 slice-CTAs (R8 bulk exchange) ----------------
__global__ __launch_bounds__(256,1) __cluster_dims__(4,1,1) void k_gru(const float* __restrict__ bhh){
    int t = threadIdx.x;       // 256
    int p = blockIdx.x >> 2;   // batch-pair group
    uint32_t s;                // slice = rank in cluster
    asm("mov.u32 %0, %%cluster_ctarank;" : "=r"(s));
    __shared__ __align__(16) unsigned long long hsu[2][128][2];  // [buf][jp][b]
    __shared__ float part[4][3][2][64];                          // [hq][gate][b][u]
    __shared__ __align__(16) float stg[2][32][2][2];             // [buf][jl2][b][par]
    __shared__ __align__(8)  unsigned long long mbar[2];
    uint32_t mb0 = smem_u32(&mbar[0]), mb1 = smem_u32(&mbar[1]);
    for(int i=t;i<512;i+=256){ ((unsigned long long*)hsu)[i] = 0ull; }
    if(t==0){ mbar_init(mb0,1); mbar_init(mb1,1); }
    __syncthreads();
    asm volatile("barrier.cluster.arrive.aligned;" ::: "memory");
    asm volatile("barrier.cluster.wait.aligned;" ::: "memory");

    int u = t&63, hq = t>>6;
    const unsigned long long* wsrc = ((const unsigned long long*)g_whhR) + (size_t)s*96*256 + t;
    unsigned long long wreg[64];
    #pragma unroll
    for(int i=0;i<64;i++) wreg[i] = wsrc[(size_t)i*256];
    const unsigned long long* wn = wsrc + (size_t)64*256;   // gate n base

    int gu = t&63, gb = (t>>6)&1;
    float bhr=0.f, bhz=0.f, bhn=0.f;
    if(t<128){
        bhr = bhh[      64*s+gu];
        bhz = bhh[256 + 64*s+gu];
        bhn = bhh[512 + 64*s+gu];
    }
    const float* gib0 = g_gi + (size_t)(2*p+gb)*WW*G3 + s*64 + gu;
    float pfr=0.f, pfz=0.f, pfn=0.f;
    if(t<128){ pfr=__ldcg(gib0); pfz=__ldcg(gib0+256); pfn=__ldcg(gib0+512); }
    int ph0=0, ph1=0;

    for(int step=0; step<WW; step++){
        int cb = step&1, nb = cb^1;
        if(step>0){
            if(cb==0){ mbar_wait(mb0, ph0); ph0^=1; }
            else     { mbar_wait(mb1, ph1); ph1^=1; }
        }
        if(t==0 && step<127) mbar_expect(nb==0? mb0 : mb1, 2048);

        unsigned long long a00=0ull,a01=0ull,a10=0ull,a11=0ull,a20=0ull,a21=0ull;
        const ulonglong2* hp = ((const ulonglong2*)hsu[cb]) + hq*32;
        #pragma unroll
        for(int jl=0;jl<32;jl++){
            ulonglong2 hv = hp[jl];
            unsigned long long wnl = __ldg(wn + (size_t)jl*256);
            fma2(a00, wreg[jl],    hv.x); fma2(a01, wreg[jl],    hv.y);
            fma2(a10, wreg[32+jl], hv.x); fma2(a11, wreg[32+jl], hv.y);
            fma2(a20, wnl,         hv.x); fma2(a21, wnl,         hv.y);
        }
        part[hq][0][0][u]=ull_sum(a00); part[hq][0][1][u]=ull_sum(a01);
        part[hq][1][0][u]=ull_sum(a10); part[hq][1][1][u]=ull_sum(a11);
        part[hq][2][0][u]=ull_sum(a20); part[hq][2][1][u]=ull_sum(a21);
        __syncthreads();
        if(t < 128){
            float gr=pfr, gz=pfz, gn=pfn;
            if(step<127){
                const float* gnx = gib0 + (size_t)(step+1)*G3;
                pfr=__ldcg(gnx); pfz=__ldcg(gnx+256); pfn=__ldcg(gnx+512);
            }
            float ghr = bhr + ((part[0][0][gb][gu]+part[1][0][gb][gu])+(part[2][0][gb][gu]+part[3][0][gb][gu]));
            float ghz = bhz + ((part[0][1][gb][gu]+part[1][1][gb][gu])+(part[2][1][gb][gu]+part[3][1][gb][gu]));
            float ghn = bhn + ((part[0][2][gb][gu]+part[1][2][gb][gu])+(part[2][2][gb][gu]+part[3][2][gb][gu]));
            float hold = ((const float*)hsu[cb])[ (((32*(int)s + (gu>>1))*2) + gb)*2 + (gu&1) ];
            float r  = sigm(gr+ghr);
            float zg = sigm(gz+ghz);
            float n  = tanh_fast(gn + r*ghn);
            float hnew = n + zg*(hold - n);
            if(step==127) g_h[(size_t)(2*p+gb)*HH + 64*s + gu] = hnew;
            else          stg[cb][gu>>1][gb][gu&1] = hnew;
        }
        __syncthreads();
        if(t<4 && step<127){
            asm volatile("fence.proxy.async.shared::cta;" ::: "memory");
            uint32_t src  = smem_u32(&stg[cb][0][0][0]);
            uint32_t dstl = smem_u32(&hsu[nb][32*(int)s][0]);
            uint32_t mbn  = nb==0 ? mb0 : mb1;
            uint32_t tr = (uint32_t)t;
            uint32_t rb = mapa_u32(mbn, tr);
            dsmem_bulk(mapa_u32(dstl, tr), src, 512, rb);
        }
    }
}

// ---------------- MLP head ----------------
__global__ void k_mlp(const float* __restrict__ b0, const float* __restrict__ b1,
                      const float* __restrict__ b2, const float* __restrict__ b3,
                      float* __restrict__ out){
    int b = blockIdx.x; int t = threadIdx.x; // 256
    __shared__ float va[FHD], vb[FHD];
    va[t] = g_h[b*HH + t];
    __syncthreads();
    float p0=0.f,p1=0.f,p2=0.f,p3=0.f;
    #pragma unroll 4
    for(int j=0;j<HH;j+=4){
        p0 += va[j  ]*g_fc0T[(j  )*FHD + t];
        p1 += va[j+1]*g_fc0T[(j+1)*FHD + t];
        p2 += va[j+2]*g_fc0T[(j+2)*FHD + t];
        p3 += va[j+3]*g_fc0T[(j+3)*FHD + t];
    }
    vb[t] = fmaxf(b0[t] + ((p0+p1)+(p2+p3)), 0.f);
    __syncthreads();
    p0=p1=p2=p3=0.f;
    #pragma unroll 4
    for(int j=0;j<FHD;j+=4){
        p0 += vb[j  ]*g_fc1T[(j  )*FHD + t];
        p1 += vb[j+1]*g_fc1T[(j+1)*FHD + t];
        p2 += vb[j+2]*g_fc1T[(j+2)*FHD + t];
        p3 += vb[j+3]*g_fc1T[(j+3)*FHD + t];
    }
    va[t] = fmaxf(b1[t] + ((p0+p1)+(p2+p3)), 0.f);
    __syncthreads();
    p0=p1=p2=p3=0.f;
    #pragma unroll 4
    for(int j=0;j<FHD;j+=4){
        p0 += va[j  ]*g_fc2T[(j  )*FHD + t];
        p1 += va[j+1]*g_fc2T[(j+1)*FHD + t];
        p2 += va[j+2]*g_fc2T[(j+2)*FHD + t];
        p3 += va[j+3]*g_fc2T[(j+3)*FHD + t];
    }
    vb[t] = fmaxf(b2[t] + ((p0+p1)+(p2+p3)), 0.f);
    __syncthreads();
    if(t < 64){
        p0=p1=p2=p3=0.f;
        #pragma unroll 4
        for(int j=0;j<FHD;j+=4){
            p0 += vb[j  ]*g_fc3T[(j  )*64 + t];
            p1 += vb[j+1]*g_fc3T[(j+1)*64 + t];
            p2 += vb[j+2]*g_fc3T[(j+2)*64 + t];
            p3 += vb[j+3]*g_fc3T[(j+3)*64 + t];
        }
        out[b*64 + t] = b3[t] + ((p0+p1)+(p2+p3));
    }
}

// ---------------- launch ----------------
extern "C" void kernel_launch(void* const* d_in, const int* in_sizes, int n_in,
                              void* d_out, int out_size){
    const float* x        = (const float*)d_in[0];
    const float* conv_w   = (const float*)d_in[1];
    const float* conv_b   = (const float*)d_in[2];
    const float* flw      = (const float*)d_in[3];
    const float* flb      = (const float*)d_in[4];
    const float* fa       = (const float*)d_in[5];
    const float* fbias    = (const float*)d_in[6];
    const float* tlw      = (const float*)d_in[7];
    const float* tlb      = (const float*)d_in[8];
    const float* ta       = (const float*)d_in[9];
    const float* tbias    = (const float*)d_in[10];
    const float* wih      = (const float*)d_in[11];
    const float* whh      = (const float*)d_in[12];
    const float* bih      = (const float*)d_in[13];
    const float* bhh      = (const float*)d_in[14];
    const float* fc0_w    = (const float*)d_in[15];
    const float* fc0_b    = (const float*)d_in[16];
    const float* fc1_w    = (const float*)d_in[17];
    const float* fc1_b    = (const float*)d_in[18];
    const float* fc2_w    = (const float*)d_in[19];
    const float* fc2_b    = (const float*)d_in[20];
    const float* fc3_w    = (const float*)d_in[21];
    const float* fc3_b    = (const float*)d_in[22];
    float* out = (float*)d_out;

    static int smem_set = 0;
    if(!smem_set){
        cudaFuncSetAttribute(k_gimma, cudaFuncAttributeMaxDynamicSharedMemorySize, GI_SMEM_BYTES);
        cudaFuncSetAttribute(k_pqmma, cudaFuncAttributeMaxDynamicSharedMemorySize, PQ_SMEM_BYTES);
        smem_set = 1;
    }

    k_prep<<<2353, 256>>>(conv_w, tlw, whh, fc0_w, fc1_w, fc2_w, fc3_w, flw, flb, fa);
    k_conv<<<dim3(8, 64), 128>>>(x, conv_b);
    k_feat<<<64, 256>>>(fbias);
    k_pqmma<<<dim3(2, 64), 256, PQ_SMEM_BYTES>>>(tlw, tlb);
    k_temp<<<dim3(8, 64), 128>>>(ta, tbias);
    k_gimma<<<dim3(6, 64), 256, GI_SMEM_BYTES>>>(wih, bih);
    k_gru<<<128, 256>>>(bhh);
    k_mlp<<<64, 256>>>(fc0_b, fc1_b, fc2_b, fc3_b, out);
}

// round 17
// speedup vs baseline: 1.0896x; 1.0504x over previous
#include <cuda_runtime.h>
#include <math.h>
#include <stdint.h>

#define BB  64
#define WW  128
#define KK  64
#define KSZ 7
#define EFD 128
#define ETD 128
#define HH  256
#define FHD 256
#define G3  768   // 3*H
#define ZC  192   // 3*K

// ---------------- scratch (static device globals; no runtime alloc) ----------------
__device__ __align__(16) float g_y[BB*WW*KK];
__device__ __align__(16) float g_hfeat[BB*WW*KK];
__device__ __align__(16) float g_htemp[BB*WW*KK];
__device__ __align__(16) float g_p[BB*WW*ETD];
__device__ __align__(16) float g_q[BB*WW*ETD];
__device__ __align__(16) float g_gi[BB*WW*G3];
__device__ float g_h[BB*HH];
__device__ __align__(16) float g_cwT[KSZ*KK*KK];   // [s][i][k]
__device__ __align__(16) float g_tlwT[ETD*ETD];    // [c][e]
__device__ __align__(16) float g_whhR[4*96*256*2]; // [slice][i=g*32+jl][col=hq*64+u][par]
__device__ __align__(16) float g_fc0T[FHD*FHD];
__device__ __align__(16) float g_fc1T[FHD*FHD];
__device__ __align__(16) float g_fc2T[FHD*FHD];
__device__ __align__(16) float g_fc3T[FHD*KK];
__device__ float g_u1[WW];
__device__ float g_u2[WW];
__device__ float g_c12[2];

__device__ __forceinline__ float sigm(float x){ return 1.f/(1.f+__expf(-x)); }
__device__ __forceinline__ float tanh_fast(float x){
    float e2 = __expf(2.f*x);
    return 1.f - 2.f/(e2+1.f);
}
__device__ __forceinline__ float lrelu(float v){ return fmaxf(v, 0.2f*v); } // ALPHA=0.2<1

__device__ __forceinline__ uint32_t smem_u32(const void* p){
    uint32_t a;
    asm("{ .reg .u64 t0; cvta.to.shared.u64 t0, %1; cvt.u32.u64 %0, t0; }" : "=r"(a) : "l"(p));
    return a;
}
__device__ __forceinline__ void fma2(unsigned long long& a, unsigned long long w, unsigned long long h){
    asm("fma.rn.f32x2 %0, %1, %2, %0;" : "+l"(a) : "l"(w), "l"(h));
}
__device__ __forceinline__ float ull_sum(unsigned long long v){
    unsigned lo, hi;
    asm("mov.b64 {%0,%1}, %2;" : "=r"(lo), "=r"(hi) : "l"(v));
    return __uint_as_float(lo) + __uint_as_float(hi);
}
__device__ __forceinline__ unsigned long long bcast2(float v){
    unsigned long long r;
    asm("mov.b64 %0, {%1, %1};" : "=l"(r) : "r"(__float_as_uint(v)));
    return r;
}
__device__ __forceinline__ void mbar_init(uint32_t mb, uint32_t cnt){
    asm volatile("mbarrier.init.shared.b64 [%0], %1;" :: "r"(mb), "r"(cnt) : "memory");
}
__device__ __forceinline__ void mbar_expect(uint32_t mb, uint32_t tx){
    asm volatile("mbarrier.arrive.expect_tx.shared.b64 _, [%0], %1;" :: "r"(mb), "r"(tx) : "memory");
}
__device__ __forceinline__ void mbar_wait(uint32_t mb, int parity){
    asm volatile(
        "{\n\t.reg .pred P1;\n\t"
        "WL_%=:\n\t"
        "mbarrier.try_wait.parity.acquire.cta.shared::cta.b64 P1, [%0], %1, 0x989680;\n\t"
        "@P1 bra.uni WD_%=;\n\t"
        "bra.uni WL_%=;\n\t"
        "WD_%=:\n\t}"
        :: "r"(mb), "r"(parity) : "memory");
}
__device__ __forceinline__ uint32_t mapa_u32(uint32_t a, uint32_t rank){
    uint32_t r;
    asm("mapa.shared::cluster.u32 %0, %1, %2;" : "=r"(r) : "r"(a), "r"(rank));
    return r;
}
__device__ __forceinline__ void dsmem_bulk(uint32_t dst, uint32_t src, uint32_t bytes, uint32_t rbar){
    asm volatile("cp.async.bulk.shared::cluster.shared::cta.mbarrier::complete_tx::bytes [%0], [%1], %2, [%3];"
                 :: "r"(dst), "r"(src), "r"(bytes), "r"(rbar) : "memory");
}
__device__ __forceinline__ uint32_t to_tf32(float v){
    uint32_t r;
    asm("cvt.rna.tf32.f32 %0, %1;" : "=r"(r) : "f"(v));
    return r;
}
__device__ __forceinline__ void mma_tf32_16x8x8(float& d0, float& d1, float& d2, float& d3,
                                                uint32_t a0, uint32_t a1, uint32_t a2, uint32_t a3,
                                                uint32_t b0, uint32_t b1){
    asm volatile("mma.sync.aligned.m16n8k8.row.col.f32.tf32.tf32.f32 "
                 "{%0,%1,%2,%3}, {%4,%5,%6,%7}, {%8,%9}, {%0,%1,%2,%3};"
                 : "+f"(d0), "+f"(d1), "+f"(d2), "+f"(d3)
                 : "r"(a0), "r"(a1), "r"(a2), "r"(a3), "r"(b0), "r"(b1));
}

// ---------------- weight reshapes / transposes + u1/u2/c12 ----------------
__global__ void k_prep(const float* __restrict__ conv_w, const float* __restrict__ tlw,
                       const float* __restrict__ whh,
                       const float* __restrict__ fc0, const float* __restrict__ fc1,
                       const float* __restrict__ fc2, const float* __restrict__ fc3,
                       const float* __restrict__ flw, const float* __restrict__ flb,
                       const float* __restrict__ fa){
    int idx = blockIdx.x*blockDim.x + threadIdx.x;
    if(idx < 28672){
        int k = idx/448; int rem = idx - k*448; int i = rem/7; int s = rem - i*7;
        g_cwT[(s*64+i)*64 + k] = conv_w[idx];
        return;
    }
    idx -= 28672;
    if(idx < 16384){
        int e = idx>>7, c = idx&127;
        g_tlwT[c*128 + e] = tlw[idx];
        return;
    }
    idx -= 16384;
    if(idx < 196608){
        int o = idx>>8, j = idx&255;
        int g = o>>8;
        int ou = o&255;
        int s = ou>>6, u = ou&63;
        int hq = j>>6;
        int jl = (j&63)>>1;
        int par = j&1;
        int d = (s*96 + g*32 + jl)*256 + (hq*64 + u);
        g_whhR[d*2 + par] = whh[idx];
        return;
    }
    idx -= 196608;
    if(idx < 65536){ int o = idx>>8, j = idx&255; g_fc0T[j*256+o] = fc0[idx]; return; }
    idx -= 65536;
    if(idx < 65536){ int o = idx>>8, j = idx&255; g_fc1T[j*256+o] = fc1[idx]; return; }
    idx -= 65536;
    if(idx < 65536){ int o = idx>>8, j = idx&255; g_fc2T[j*256+o] = fc2[idx]; return; }
    idx -= 65536;
    if(idx < 16384){ int o = idx>>8, j = idx&255; g_fc3T[j*64+o] = fc3[idx]; return; }
    idx -= 16384;
    if(idx < 128){
        float a1=0.f, a2=0.f;
        for(int e=0;e<EFD;e++){ float w = flw[e*WW + idx]; a1 += w*fa[e]; a2 += w*fa[EFD+e]; }
        g_u1[idx]=a1; g_u2[idx]=a2;
        return;
    }
    if(idx==128){ float c=0.f; for(int e=0;e<EFD;e++) c += flb[e]*fa[e];     g_c12[0]=c; return; }
    if(idx==129){ float c=0.f; for(int e=0;e<EFD;e++) c += flb[e]*fa[EFD+e]; g_c12[1]=c; return; }
}

// ---------------- conv1d (pad=3) + relu -> y[b,w,k] ; f32x2 over k-pairs ----------------
__global__ void k_conv(const float* __restrict__ x, const float* __restrict__ conv_b){
    int b = blockIdx.y; int w0 = blockIdx.x*16;
    int t = threadIdx.x; // 128
    int kp = t&31, wq = t>>5;
    __shared__ float xs[22*64];
    for(int i=t; i<22*64; i+=128){
        int row = w0-3+(i>>6);
        xs[i] = (row>=0 && row<WW) ? x[(b*WW+row)*KK + (i&63)] : 0.f;
    }
    __syncthreads();
    unsigned long long acc[4];
    {
        float2 b2 = *(const float2*)(conv_b + 2*kp);
        unsigned long long bb;
        asm("mov.b64 %0, {%1, %2};" : "=l"(bb) : "r"(__float_as_uint(b2.x)), "r"(__float_as_uint(b2.y)));
        #pragma unroll
        for(int r=0;r<4;r++) acc[r]=bb;
    }
    #pragma unroll
    for(int s=0;s<KSZ;s++){
        #pragma unroll 8
        for(int i=0;i<KK;i++){
            unsigned long long cw2 = *(const unsigned long long*)(g_cwT + (s*64+i)*64 + 2*kp);
            #pragma unroll
            for(int r=0;r<4;r++){
                unsigned long long xx = bcast2(xs[(wq*4+r+s)*64 + i]);
                fma2(acc[r], cw2, xx);
            }
        }
    }
    #pragma unroll
    for(int r=0;r<4;r++){
        unsigned lo, hi;
        asm("mov.b64 {%0,%1}, %2;" : "=r"(lo), "=r"(hi) : "l"(acc[r]));
        float2 o;
        o.x = fmaxf(__uint_as_float(lo), 0.f);
        o.y = fmaxf(__uint_as_float(hi), 0.f);
        *(float2*)(g_y + (size_t)(b*WW + w0 + wq*4 + r)*KK + 2*kp) = o;
    }
}

// ---------------- feature attention + h_feat (s1/s2 fused in) ----------------
__global__ __launch_bounds__(256) void k_feat(const float* __restrict__ feat_bias){
    int b = blockIdx.x; int t = threadIdx.x; // 256
    __shared__ float ys[WW*KK];
    __shared__ float att[KK*KK];
    __shared__ float u1s[WW], u2s[WW];
    __shared__ float r1[256], r2[256];
    __shared__ float s1s[64], s2s[64];
    if(t<128){ u1s[t]=g_u1[t]; u2s[t]=g_u2[t]; }
    for(int it=0; it<32; it++){ int idx = it*256+t; ys[idx] = g_y[b*WW*KK + idx]; }
    __syncthreads();
    {
        int k = t&63, q = t>>6;
        float a1=0.f, a2=0.f;
        #pragma unroll 8
        for(int w=q*32; w<q*32+32; w++){
            float yv = ys[w*64+k];
            a1 += yv*u1s[w]; a2 += yv*u2s[w];
        }
        r1[t]=a1; r2[t]=a2;
    }
    __syncthreads();
    if(t<64){
        s1s[t] = r1[t]+r1[t+64]+r1[t+128]+r1[t+192] + g_c12[0];
        s2s[t] = r2[t]+r2[t+64]+r2[t+128]+r2[t+192] + g_c12[1];
    }
    __syncthreads();
    int lane = t&31, wd = t>>5;
    #pragma unroll
    for(int r=0;r<8;r++){
        int i = wd*8 + r;
        float s1v = s1s[i];
        int j0 = lane, j1 = lane+32;
        float v0 = lrelu(s1v + s2s[j0]) + feat_bias[i*64+j0];
        float v1 = lrelu(s1v + s2s[j1]) + feat_bias[i*64+j1];
        float m = fmaxf(v0,v1);
        #pragma unroll
        for(int off=16;off;off>>=1) m = fmaxf(m, __shfl_xor_sync(0xffffffffu, m, off));
        float e0 = __expf(v0-m), e1 = __expf(v1-m);
        float ssum = e0+e1;
        #pragma unroll
        for(int off=16;off;off>>=1) ssum += __shfl_xor_sync(0xffffffffu, ssum, off);
        float inv = 1.f/ssum;
        att[j0*64+i] = e0*inv;
        att[j1*64+i] = e1*inv;
    }
    __syncthreads();
    int i = t&63, wofs = t>>6;
    for(int wl=0; wl<16; wl++){
        int wA = (wl*2  )*4 + wofs;
        int wB = (wl*2+1)*4 + wofs;
        float accA = 0.f, accB = 0.f;
        #pragma unroll 8
        for(int j=0;j<64;j++){
            float av = att[j*64+i];
            accA += av*ys[wA*64+j];
            accB += av*ys[wB*64+j];
        }
        g_hfeat[(b*WW+wA)*KK + i] = sigm(accA);
        g_hfeat[(b*WW+wB)*KK + i] = sigm(accB);
    }
}

// ---------------- p,q via warp-level mma.sync tf32 ----------------
#define PQ_LD 68
#define PQ_SMEM_BYTES (2*128*PQ_LD*4)

__global__ __launch_bounds__(256,1) void k_pqmma(const float* __restrict__ tlw,
                                                 const float* __restrict__ tlb){
    extern __shared__ __align__(16) uint32_t psm[];
    uint32_t* sA = psm;                 // y rows [128][PQ_LD]
    uint32_t* sB = psm + 128*PQ_LD;     // W rows [128][PQ_LD]
    int t = threadIdx.x;                // 256
    int half = blockIdx.x;              // 0 -> p, 1 -> q
    int b = blockIdx.y;

    for(int i=t; i<128*16; i+=256){
        int row = i>>4, c4 = i&15;
        float4 v = *(const float4*)(g_y + (size_t)(b*WW+row)*KK + c4*4);
        uint32_t* d = sA + row*PQ_LD + c4*4;
        d[0]=to_tf32(v.x); d[1]=to_tf32(v.y); d[2]=to_tf32(v.z); d[3]=to_tf32(v.w);
    }
    for(int i=t; i<128*16; i+=256){
        int n = i>>4, c4 = i&15;
        float4 v = *(const float4*)(tlw + n*128 + half*64 + c4*4);
        uint32_t* d = sB + n*PQ_LD + c4*4;
        d[0]=to_tf32(v.x); d[1]=to_tf32(v.y); d[2]=to_tf32(v.z); d[3]=to_tf32(v.w);
    }
    __syncthreads();

    int w = t>>5, lane = t&31;
    int wm = (w>>1)*32, wn = (w&1)*64;
    int lr = lane>>2, lc = lane&3;

    float d[2][8][4];
    #pragma unroll
    for(int mt=0;mt<2;mt++)
        #pragma unroll
        for(int nt=0;nt<8;nt++)
            #pragma unroll
            for(int k=0;k<4;k++) d[mt][nt][k]=0.f;

    #pragma unroll
    for(int ks=0; ks<8; ks++){
        int k0 = ks*8;
        uint32_t a[2][4];
        #pragma unroll
        for(int mt=0;mt<2;mt++){
            const uint32_t* ab = sA + (wm + mt*16 + lr)*PQ_LD + k0 + lc;
            a[mt][0] = ab[0];
            a[mt][1] = ab[8*PQ_LD];
            a[mt][2] = ab[4];
            a[mt][3] = ab[8*PQ_LD + 4];
        }
        uint32_t bfr[8][2];
        #pragma unroll
        for(int nt=0;nt<8;nt++){
            const uint32_t* bb = sB + (wn + nt*8 + lr)*PQ_LD + k0 + lc;
            bfr[nt][0] = bb[0];
            bfr[nt][1] = bb[4];
        }
        #pragma unroll
        for(int mt=0;mt<2;mt++)
            #pragma unroll
            for(int nt=0;nt<8;nt++)
                mma_tf32_16x8x8(d[mt][nt][0], d[mt][nt][1], d[mt][nt][2], d[mt][nt][3],
                                a[mt][0], a[mt][1], a[mt][2], a[mt][3],
                                bfr[nt][0], bfr[nt][1]);
    }

    float* dstb = half==0 ? g_p : g_q;
    #pragma unroll
    for(int mt=0;mt<2;mt++){
        int row0 = wm + mt*16 + lr;
        float* dst0 = dstb + (size_t)(b*WW + row0)*ETD;
        float* dst1 = dstb + (size_t)(b*WW + row0 + 8)*ETD;
        #pragma unroll
        for(int nt=0;nt<8;nt++){
            int col = wn + nt*8 + 2*lc;
            float2 bv = (half==0) ? *(const float2*)(tlb + col) : make_float2(0.f,0.f);
            *(float2*)(dst0 + col) = make_float2(d[mt][nt][0]+bv.x, d[mt][nt][1]+bv.y);
            *(float2*)(dst1 + col) = make_float2(d[mt][nt][2]+bv.x, d[mt][nt][3]+bv.y);
        }
    }
}

// ---------------- temporal attention + h_temp (16 i's per block) ----------------
__global__ __launch_bounds__(128) void k_temp(const float* __restrict__ temp_a, const float* __restrict__ temp_bias){
    int i0 = blockIdx.x*16; int b = blockIdx.y; int t = threadIdx.x; // 128 (= j)
    __shared__ __align__(16) float psst[16*128];
    __shared__ __align__(16) float ta6[128];
    __shared__ __align__(16) float ta4[128];
    __shared__ __align__(16) float atts[128*16];
    __shared__ float wr[16*4];
    __shared__ float hb[64*16];
    {
        float tv = temp_a[t];
        ta6[t] = 0.6f*tv;
        ta4[t] = 0.4f*tv;
    }
    #pragma unroll
    for(int r=0;r<16;r++) psst[r*128+t] = g_p[(b*WW+i0+r)*ETD + t];
    __syncthreads();
    const float4* q4 = (const float4*)(g_q + (size_t)(b*WW+t)*ETD);
    float eja[16], ejb[16];
    #pragma unroll
    for(int i=0;i<16;i++){ eja[i] = temp_bias[(i0+i)*WW + t]; ejb[i]=0.f; }
    for(int c=0;c<32;c++){
        float4 qv = q4[c];
        float4 a6 = *(const float4*)(ta6 + 4*c);
        float4 a4 = *(const float4*)(ta4 + 4*c);
        #pragma unroll
        for(int i=0;i<16;i++){
            float4 pv = *(const float4*)(psst + i*128 + 4*c);
            float v0 = pv.x+qv.x, v1 = pv.y+qv.y, v2 = pv.z+qv.z, v3 = pv.w+qv.w;
            eja[i] = fmaf(a6.x, v0, eja[i]); ejb[i] = fmaf(a4.x, fabsf(v0), ejb[i]);
            eja[i] = fmaf(a6.y, v1, eja[i]); ejb[i] = fmaf(a4.y, fabsf(v1), ejb[i]);
            eja[i] = fmaf(a6.z, v2, eja[i]); ejb[i] = fmaf(a4.z, fabsf(v2), ejb[i]);
            eja[i] = fmaf(a6.w, v3, eja[i]); ejb[i] = fmaf(a4.w, fabsf(v3), ejb[i]);
        }
    }
    float ej[16];
    #pragma unroll
    for(int i=0;i<16;i++) ej[i] = eja[i]+ejb[i];
    int lane = t&31, wd = t>>5;
    #pragma unroll
    for(int i=0;i<16;i++){
        float m = ej[i];
        #pragma unroll
        for(int off=16;off;off>>=1) m = fmaxf(m, __shfl_xor_sync(0xffffffffu, m, off));
        if(lane==0) wr[i*4+wd]=m;
    }
    __syncthreads();
    float mx[16];
    #pragma unroll
    for(int i=0;i<16;i++) mx[i] = fmaxf(fmaxf(wr[i*4],wr[i*4+1]), fmaxf(wr[i*4+2],wr[i*4+3]));
    __syncthreads();
    #pragma unroll
    for(int i=0;i<16;i++){
        float e = __expf(ej[i]-mx[i]); ej[i]=e;
        float ss = e;
        #pragma unroll
        for(int off=16;off;off>>=1) ss += __shfl_xor_sync(0xffffffffu, ss, off);
        if(lane==0) wr[i*4+wd]=ss;
    }
    __syncthreads();
    #pragma unroll
    for(int i=0;i<16;i++){
        float ss = wr[i*4]+wr[i*4+1]+wr[i*4+2]+wr[i*4+3];
        atts[t*16+i] = ej[i]/ss;
    }
    __syncthreads();
    int k = t&63, half = t>>6;
    float acc[16];
    #pragma unroll
    for(int i=0;i<16;i++) acc[i]=0.f;
    for(int j=0;j<64;j++){
        int jj = half*64+j;
        float yv = g_y[(b*WW+jj)*KK + k];
        const float4* a4 = (const float4*)(atts + jj*16);
        #pragma unroll
        for(int c4=0;c4<4;c4++){
            float4 av = a4[c4];
            acc[c4*4+0]+=av.x*yv; acc[c4*4+1]+=av.y*yv;
            acc[c4*4+2]+=av.z*yv; acc[c4*4+3]+=av.w*yv;
        }
    }
    if(half==1){
        #pragma unroll
        for(int i=0;i<16;i++) hb[k*16+i]=acc[i];
    }
    __syncthreads();
    if(half==0){
        #pragma unroll
        for(int i=0;i<16;i++){
            float v = acc[i] + hb[k*16+i];
            g_htemp[(b*WW+i0+i)*KK + k] = sigm(v);
        }
    }
}

// ---------------- gi = Z @ wih^T + bih via warp-level mma.sync tf32 ----------------
#define GI_LD  196
#define GI_SMEM_BYTES (2*128*GI_LD*4)

__global__ __launch_bounds__(256,1) void k_gimma(const float* __restrict__ wih,
                                                 const float* __restrict__ bih){
    extern __shared__ __align__(16) uint32_t gsm[];
    uint32_t* sA = gsm;
    uint32_t* sB = gsm + 128*GI_LD;
    int t = threadIdx.x;
    int b  = blockIdx.y;
    int n0 = blockIdx.x * 128;

    for(int i=t; i<128*48; i+=256){
        int row = i/48, c4 = i - row*48;
        int kk = c4*4;
        int base = (b*WW+row)*KK;
        const float* src;
        if(kk<64)       src = g_y     + base + kk;
        else if(kk<128) src = g_hfeat + base + kk-64;
        else            src = g_htemp + base + kk-128;
        float4 v = *(const float4*)src;
        uint32_t* d = sA + row*GI_LD + kk;
        d[0]=to_tf32(v.x); d[1]=to_tf32(v.y); d[2]=to_tf32(v.z); d[3]=to_tf32(v.w);
    }
    for(int i=t; i<128*48; i+=256){
        int row = i/48, c4 = i - row*48;
        float4 v = *(const float4*)(wih + (size_t)(n0+row)*ZC + c4*4);
        uint32_t* d = sB + row*GI_LD + c4*4;
        d[0]=to_tf32(v.x); d[1]=to_tf32(v.y); d[2]=to_tf32(v.z); d[3]=to_tf32(v.w);
    }
    __syncthreads();

    int w = t>>5, lane = t&31;
    int wm = (w>>1)*32;
    int wn = (w&1)*64;
    int lr = lane>>2, lc = lane&3;

    float d[2][8][4];
    #pragma unroll
    for(int mt=0;mt<2;mt++)
        #pragma unroll
        for(int nt=0;nt<8;nt++)
            #pragma unroll
            for(int k=0;k<4;k++) d[mt][nt][k]=0.f;

    #pragma unroll 4
    for(int ks=0; ks<24; ks++){
        int k0 = ks*8;
        uint32_t a[2][4];
        #pragma unroll
        for(int mt=0;mt<2;mt++){
            const uint32_t* ab = sA + (wm + mt*16 + lr)*GI_LD + k0 + lc;
            a[mt][0] = ab[0];
            a[mt][1] = ab[8*GI_LD];
            a[mt][2] = ab[4];
            a[mt][3] = ab[8*GI_LD + 4];
        }
        uint32_t bfr[8][2];
        #pragma unroll
        for(int nt=0;nt<8;nt++){
            const uint32_t* bb = sB + (wn + nt*8 + lr)*GI_LD + k0 + lc;
            bfr[nt][0] = bb[0];
            bfr[nt][1] = bb[4];
        }
        #pragma unroll
        for(int mt=0;mt<2;mt++)
            #pragma unroll
            for(int nt=0;nt<8;nt++)
                mma_tf32_16x8x8(d[mt][nt][0], d[mt][nt][1], d[mt][nt][2], d[mt][nt][3],
                                a[mt][0], a[mt][1], a[mt][2], a[mt][3],
                                bfr[nt][0], bfr[nt][1]);
    }

    #pragma unroll
    for(int mt=0;mt<2;mt++){
        int row0 = wm + mt*16 + lr;
        float* dst0 = g_gi + (size_t)(b*WW + row0)*G3 + n0;
        float* dst1 = g_gi + (size_t)(b*WW + row0 + 8)*G3 + n0;
        #pragma unroll
        for(int nt=0;nt<8;nt++){
            int col = wn + nt*8 + 2*lc;
            float2 bv = *(const float2*)(bih + n0 + col);
            *(float2*)(dst0 + col) = make_float2(d[mt][nt][0]+bv.x, d[mt][nt][1]+bv.y);
            *(float2*)(dst1 + col) = make_float2(d[mt][nt][2]+bv.x, d[mt][nt][3]+bv.y);
        }
    }
}

// ---------------- GRU: 32 clusters x 4 slice-CTAs; 80/16 reg/stream weight split ----------------
__global__ __launch_bounds__(256,1) __cluster_dims__(4,1,1) void k_gru(const float* __restrict__ bhh){
    int t = threadIdx.x;       // 256
    int p = blockIdx.x >> 2;   // batch-pair group
    uint32_t s;                // slice = rank in cluster
    asm("mov.u32 %0, %%cluster_ctarank;" : "=r"(s));
    __shared__ __align__(16) unsigned long long hsu[2][128][2];  // [buf][jp][b]
    __shared__ float part[4][3][2][64];                          // [hq][gate][b][u]
    __shared__ __align__(16) float stg[2][32][2][2];             // [buf][jl2][b][par]
    __shared__ __align__(8)  unsigned long long mbar[2];
    uint32_t mb0 = smem_u32(&mbar[0]), mb1 = smem_u32(&mbar[1]);
    for(int i=t;i<512;i+=256){ ((unsigned long long*)hsu)[i] = 0ull; }
    if(t==0){ mbar_init(mb0,1); mbar_init(mb1,1); }
    __syncthreads();
    asm volatile("barrier.cluster.arrive.aligned;" ::: "memory");
    asm volatile("barrier.cluster.wait.aligned;" ::: "memory");

    int u = t&63, hq = t>>6;
    // preload rows 0..79: gate r (0..31), gate z (32..63), gate n jl 0..15 (64..79)
    const unsigned long long* wsrc = ((const unsigned long long*)g_whhR) + (size_t)s*96*256 + t;
    unsigned long long wreg[80];
    #pragma unroll
    for(int i=0;i<80;i++) wreg[i] = wsrc[(size_t)i*256];
    const unsigned long long* wn = wsrc + (size_t)64*256;   // gate n base (jl indexed)

    int gu = t&63, gb = (t>>6)&1;
    float bhr=0.f, bhz=0.f, bhn=0.f;
    if(t<128){
        bhr = bhh[      64*s+gu];
        bhz = bhh[256 + 64*s+gu];
        bhn = bhh[512 + 64*s+gu];
    }
    const float* gib0 = g_gi + (size_t)(2*p+gb)*WW*G3 + s*64 + gu;
    float pfr=0.f, pfz=0.f, pfn=0.f;
    if(t<128){ pfr=__ldcg(gib0); pfz=__ldcg(gib0+256); pfn=__ldcg(gib0+512); }
    int ph0=0, ph1=0;

    for(int step=0; step<WW; step++){
        int cb = step&1, nb = cb^1;
        if(step>0){
            if(cb==0){ mbar_wait(mb0, ph0); ph0^=1; }
            else     { mbar_wait(mb1, ph1); ph1^=1; }
        }
        if(t==0 && step<127) mbar_expect(nb==0? mb0 : mb1, 2048);

        unsigned long long a00=0ull,a01=0ull,a10=0ull,a11=0ull,a20=0ull,a21=0ull;
        const ulonglong2* hp = ((const ulonglong2*)hsu[cb]) + hq*32;
        #pragma unroll
        for(int jl=0;jl<16;jl++){
            ulonglong2 hv = hp[jl];
            fma2(a00, wreg[jl],    hv.x); fma2(a01, wreg[jl],    hv.y);
            fma2(a10, wreg[32+jl], hv.x); fma2(a11, wreg[32+jl], hv.y);
            fma2(a20, wreg[64+jl], hv.x); fma2(a21, wreg[64+jl], hv.y);
        }
        #pragma unroll
        for(int jl=16;jl<32;jl++){
            ulonglong2 hv = hp[jl];
            unsigned long long wnl = __ldg(wn + (size_t)jl*256);
            fma2(a00, wreg[jl],    hv.x); fma2(a01, wreg[jl],    hv.y);
            fma2(a10, wreg[32+jl], hv.x); fma2(a11, wreg[32+jl], hv.y);
            fma2(a20, wnl,         hv.x); fma2(a21, wnl,         hv.y);
        }
        part[hq][0][0][u]=ull_sum(a00); part[hq][0][1][u]=ull_sum(a01);
        part[hq][1][0][u]=ull_sum(a10); part[hq][1][1][u]=ull_sum(a11);
        part[hq][2][0][u]=ull_sum(a20); part[hq][2][1][u]=ull_sum(a21);
        __syncthreads();
        if(t < 128){
            float gr=pfr, gz=pfz, gn=pfn;
            if(step<127){
                const float* gnx = gib0 + (size_t)(step+1)*G3;
                pfr=__ldcg(gnx); pfz=__ldcg(gnx+256); pfn=__ldcg(gnx+512);
            }
            float ghr = bhr + ((part[0][0][gb][gu]+part[1][0][gb][gu])+(part[2][0][gb][gu]+part[3][0][gb][gu]));
            float ghz = bhz + ((part[0][1][gb][gu]+part[1][1][gb][gu])+(part[2][1][gb][gu]+part[3][1][gb][gu]));
            float ghn = bhn + ((part[0][2][gb][gu]+part[1][2][gb][gu])+(part[2][2][gb][gu]+part[3][2][gb][gu]));
            float hold = ((const float*)hsu[cb])[ (((32*(int)s + (gu>>1))*2) + gb)*2 + (gu&1) ];
            float r  = sigm(gr+ghr);
            float zg = sigm(gz+ghz);
            float n  = tanh_fast(gn + r*ghn);
            float hnew = n + zg*(hold - n);
            if(step==127) g_h[(size_t)(2*p+gb)*HH + 64*s + gu] = hnew;
            else          stg[cb][gu>>1][gb][gu&1] = hnew;
        }
        __syncthreads();
        if(t<4 && step<127){
            asm volatile("fence.proxy.async.shared::cta;" ::: "memory");
            uint32_t src  = smem_u32(&stg[cb][0][0][0]);
            uint32_t dstl = smem_u32(&hsu[nb][32*(int)s][0]);
            uint32_t mbn  = nb==0 ? mb0 : mb1;
            uint32_t tr = (uint32_t)t;
            uint32_t rb = mapa_u32(mbn, tr);
            dsmem_bulk(mapa_u32(dstl, tr), src, 512, rb);
        }
    }
}

// ---------------- MLP head ----------------
__global__ void k_mlp(const float* __restrict__ b0, const float* __restrict__ b1,
                      const float* __restrict__ b2, const float* __restrict__ b3,
                      float* __restrict__ out){
    int b = blockIdx.x; int t = threadIdx.x; // 256
    __shared__ float va[FHD], vb[FHD];
    va[t] = g_h[b*HH + t];
    __syncthreads();
    float p0=0.f,p1=0.f,p2=0.f,p3=0.f;
    #pragma unroll 4
    for(int j=0;j<HH;j+=4){
        p0 += va[j  ]*g_fc0T[(j  )*FHD + t];
        p1 += va[j+1]*g_fc0T[(j+1)*FHD + t];
        p2 += va[j+2]*g_fc0T[(j+2)*FHD + t];
        p3 += va[j+3]*g_fc0T[(j+3)*FHD + t];
    }
    vb[t] = fmaxf(b0[t] + ((p0+p1)+(p2+p3)), 0.f);
    __syncthreads();
    p0=p1=p2=p3=0.f;
    #pragma unroll 4
    for(int j=0;j<FHD;j+=4){
        p0 += vb[j  ]*g_fc1T[(j  )*FHD + t];
        p1 += vb[j+1]*g_fc1T[(j+1)*FHD + t];
        p2 += vb[j+2]*g_fc1T[(j+2)*FHD + t];
        p3 += vb[j+3]*g_fc1T[(j+3)*FHD + t];
    }
    va[t] = fmaxf(b1[t] + ((p0+p1)+(p2+p3)), 0.f);
    __syncthreads();
    p0=p1=p2=p3=0.f;
    #pragma unroll 4
    for(int j=0;j<FHD;j+=4){
        p0 += va[j  ]*g_fc2T[(j  )*FHD + t];
        p1 += va[j+1]*g_fc2T[(j+1)*FHD + t];
        p2 += va[j+2]*g_fc2T[(j+2)*FHD + t];
        p3 += va[j+3]*g_fc2T[(j+3)*FHD + t];
    }
    vb[t] = fmaxf(b2[t] + ((p0+p1)+(p2+p3)), 0.f);
    __syncthreads();
    if(t < 64){
        p0=p1=p2=p3=0.f;
        #pragma unroll 4
        for(int j=0;j<FHD;j+=4){
            p0 += vb[j  ]*g_fc3T[(j  )*64 + t];
            p1 += vb[j+1]*g_fc3T[(j+1)*64 + t];
            p2 += vb[j+2]*g_fc3T[(j+2)*64 + t];
            p3 += vb[j+3]*g_fc3T[(j+3)*64 + t];
        }
        out[b*64 + t] = b3[t] + ((p0+p1)+(p2+p3));
    }
}

// ---------------- launch ----------------
extern "C" void kernel_launch(void* const* d_in, const int* in_sizes, int n_in,
                              void* d_out, int out_size){
    const float* x        = (const float*)d_in[0];
    const float* conv_w   = (const float*)d_in[1];
    const float* conv_b   = (const float*)d_in[2];
    const float* flw      = (const float*)d_in[3];
    const float* flb      = (const float*)d_in[4];
    const float* fa       = (const float*)d_in[5];
    const float* fbias    = (const float*)d_in[6];
    const float* tlw      = (const float*)d_in[7];
    const float* tlb      = (const float*)d_in[8];
    const float* ta       = (const float*)d_in[9];
    const float* tbias    = (const float*)d_in[10];
    const float* wih      = (const float*)d_in[11];
    const float* whh      = (const float*)d_in[12];
    const float* bih      = (const float*)d_in[13];
    const float* bhh      = (const float*)d_in[14];
    const float* fc0_w    = (const float*)d_in[15];
    const float* fc0_b    = (const float*)d_in[16];
    const float* fc1_w    = (const float*)d_in[17];
    const float* fc1_b    = (const float*)d_in[18];
    const float* fc2_w    = (const float*)d_in[19];
    const float* fc2_b    = (const float*)d_in[20];
    const float* fc3_w    = (const float*)d_in[21];
    const float* fc3_b    = (const float*)d_in[22];
    float* out = (float*)d_out;

    static int smem_set = 0;
    if(!smem_set){
        cudaFuncSetAttribute(k_gimma, cudaFuncAttributeMaxDynamicSharedMemorySize, GI_SMEM_BYTES);
        cudaFuncSetAttribute(k_pqmma, cudaFuncAttributeMaxDynamicSharedMemorySize, PQ_SMEM_BYTES);
        smem_set = 1;
    }

    k_prep<<<2353, 256>>>(conv_w, tlw, whh, fc0_w, fc1_w, fc2_w, fc3_w, flw, flb, fa);
    k_conv<<<dim3(8, 64), 128>>>(x, conv_b);
    k_feat<<<64, 256>>>(fbias);
    k_pqmma<<<dim3(2, 64), 256, PQ_SMEM_BYTES>>>(tlw, tlb);
    k_temp<<<dim3(8, 64), 128>>>(ta, tbias);
    k_gimma<<<dim3(6, 64), 256, GI_SMEM_BYTES>>>(wih, bih);
    k_gru<<<128, 256>>>(bhh);
    k_mlp<<<64, 256>>>(fc0_b, fc1_b, fc2_b, fc3_b, out);
}